// round 13
// baseline (speedup 1.0000x reference)
#include <cuda_runtime.h>
#include <cuda_fp16.h>
#include <math.h>
#include <stdint.h>

// ---------------- problem constants ----------------
#define B_    8
#define T_    4096
#define DIM_  1024
#define DIN_  512
#define DBR_  256
#define HBR_  8
#define TP_   4100
#define NW1_  410
#define NW2_  205

// ---------------- device scratch (static) ----------------
__device__ __half g_xh  [B_*T_*DIM_];
__device__ float  g_xi  [B_*T_*DIN_];
__device__ __half g_xih [B_*T_*DIN_];
__device__ __half g_qkv1[B_*TP_*3*DBR_];
__device__ __half g_qkv2[B_*TP_*3*DBR_];
__device__ __half g_ao1 [B_*TP_*DBR_];
__device__ __half g_ao2 [B_*TP_*DBR_];
__device__ __half g_xcat[B_*T_*DIN_];
__device__ float  g_xmid[B_*T_*DIM_];
__device__ __half g_h   [B_*T_*DIM_];
__device__ __half g_ffn [B_*T_*2*DIM_];
__device__ __half g_wt  [5767168];

#define O_DOWN  0u
#define O_UP    524288u
#define O_QKV1  1048576u
#define O_QKV2  1245184u
#define O_PROJ1 1441792u
#define O_PROJ2 1507328u
#define O_FFN1  1572864u
#define O_FFN2  3670016u

// ---------------- PTX helpers ----------
__device__ __forceinline__ uint32_t smem_u32(const void* p) {
    uint32_t a;
    asm("{ .reg .u64 t; cvta.to.shared.u64 t, %1; cvt.u32.u64 %0, t; }" : "=r"(a) : "l"(p));
    return a;
}
__device__ __forceinline__ uint32_t h2pack(float lo, float hi) {
    __half2 h = __floats2half2_rn(lo, hi);
    return *reinterpret_cast<uint32_t*>(&h);
}
__device__ __forceinline__ void mma_f16(float* d, const uint32_t* a, const uint32_t* b) {
    asm volatile(
        "mma.sync.aligned.m16n8k16.row.col.f32.f16.f16.f32 "
        "{%0,%1,%2,%3}, {%4,%5,%6,%7}, {%8,%9}, {%0,%1,%2,%3};"
        : "+f"(d[0]), "+f"(d[1]), "+f"(d[2]), "+f"(d[3])
        : "r"(a[0]), "r"(a[1]), "r"(a[2]), "r"(a[3]), "r"(b[0]), "r"(b[1]));
}
__device__ __forceinline__ void ldsm_x4(uint32_t* r, uint32_t addr) {
    asm volatile("ldmatrix.sync.aligned.m8n8.x4.shared.b16 {%0,%1,%2,%3}, [%4];"
                 : "=r"(r[0]), "=r"(r[1]), "=r"(r[2]), "=r"(r[3]) : "r"(addr));
}
__device__ __forceinline__ void cp_async16(uint32_t dst, const void* src, int szBytes) {
    asm volatile("cp.async.cg.shared.global [%0], [%1], 16, %2;"
                 :: "r"(dst), "l"(src), "r"(szBytes));
}
__device__ __forceinline__ void cp_async16f(uint32_t dst, const void* src) {
    asm volatile("cp.async.cg.shared.global [%0], [%1], 16;"
                 :: "r"(dst), "l"(src));
}
__device__ __forceinline__ void cp_commit() { asm volatile("cp.async.commit_group;" ::: "memory"); }
__device__ __forceinline__ void cp_wait1()  { asm volatile("cp.async.wait_group 1;" ::: "memory"); }
__device__ __forceinline__ void cp_wait0()  { asm volatile("cp.async.wait_group 0;" ::: "memory"); }

// ---------------- GEMM args (pair dispatch via blockIdx.z) ----------------
struct GemmArgs {
    const __half* A[2];
    const __half* Wt[2];
    const float*  bias[2];
    const float*  res;
    void*         C[2];
    int shift[2];    // aShift (pack) or oShift (mode 4)
    int colOff[2];   // aColOff (pack) or oColOff (mode 4)
};

// ---------------- fp16-storage warp-mma GEMM (fp32 accumulate) ----------------
// CTA tile 128x256, 8 warps (2x4), warp tile 64x64, K-chunk 64, 3-stage cp.async.
// mode 0: bias, fp32 out        mode 1: bias+GELU, fp16 out
// mode 2: bias+res, fp32 out    mode 3: bias, fp16 out
// mode 4: bias, fp16 out, unshift row-remap into [B*T, DIN] at colOff
// aPack: A rows gathered from [B*T_, DIN_] via roll(+shift)+pad at colOff
#define GBM 128
#define GBN 256
#define GBK 64
#define ASTH 72
#define STAGE_H ((GBM + GBN) * ASTH)
#define GEMM_SMEM (3 * STAGE_H * 2)             // 165888 bytes

__device__ __forceinline__ void stage_loads(
    const __half* __restrict__ A, const __half* __restrict__ Wt,
    int M, int K, int rowBase, int colBase, int k0,
    uint32_t asBase, uint32_t bsBase, int tid,
    int aPack, int aShift, int aColOff)
{
    #pragma unroll
    for (int i = 0; i < 4; i++) {
        int idx = tid + i * 256;
        int r = idx >> 3, c = (idx & 7) << 3;
        int gr = rowBase + r;
        const __half* src;
        int sz;
        if (aPack) {
            int b = gr / TP_;
            int t = gr - b * TP_;
            int ts = t + aShift; if (ts >= TP_) ts -= TP_;
            sz = (gr < M && ts < T_) ? 16 : 0;
            if (ts >= T_) ts = 0;
            if (b >= B_) b = B_ - 1;
            src = A + ((size_t)b * T_ + ts) * DIN_ + aColOff + k0 + c;
        } else {
            sz = (gr < M) ? 16 : 0;
            if (gr >= M) gr = M - 1;
            src = A + (size_t)gr * K + k0 + c;
        }
        cp_async16(asBase + (uint32_t)(r * ASTH + c) * 2u, src, sz);
    }
    #pragma unroll
    for (int i = 0; i < 8; i++) {
        int idx = tid + i * 256;
        int r = idx >> 3, c = (idx & 7) << 3;
        cp_async16f(bsBase + (uint32_t)(r * ASTH + c) * 2u,
                    Wt + (size_t)(colBase + r) * K + k0 + c);
    }
    cp_commit();
}

__global__ __launch_bounds__(256, 1)
void mma_gemm(GemmArgs ga, int M, int N, int K, int mode, int aPack)
{
    extern __shared__ __half smh[];
    const uint32_t smBase = smem_u32(smh);

    const int z = blockIdx.z;
    const __half* A    = ga.A[z];
    const __half* Wt   = ga.Wt[z];
    const float*  bias = ga.bias[z];
    void*         Cv   = ga.C[z];
    const int shft   = ga.shift[z];
    const int colOff = ga.colOff[z];

    const int tid  = threadIdx.x;
    const int wid  = tid >> 5;
    const int lane = tid & 31;
    const int g    = lane >> 2;
    const int tg   = lane & 3;
    const int warpRow = wid >> 2;
    const int warpCol = wid & 3;
    const int rowBase = blockIdx.y * GBM;
    const int colBase = blockIdx.x * GBN;

    float acc[4][8][4];
    #pragma unroll
    for (int mt = 0; mt < 4; mt++)
        #pragma unroll
        for (int nt = 0; nt < 8; nt++)
            #pragma unroll
            for (int i = 0; i < 4; i++) acc[mt][nt][i] = 0.f;

    const int nk = K >> 6;
    stage_loads(A, Wt, M, K, rowBase, colBase, 0,
                smBase, smBase + GBM * ASTH * 2u, tid, aPack, shft, colOff);
    if (nk > 1) {
        const uint32_t b1 = smBase + (uint32_t)STAGE_H * 2u;
        stage_loads(A, Wt, M, K, rowBase, colBase, GBK,
                    b1, b1 + GBM * ASTH * 2u, tid, aPack, shft, colOff);
    }

    const uint32_t aLaneOff = (uint32_t)((warpRow * 64 + (lane & 15)) * ASTH + (lane >> 4) * 8) * 2u;
    const uint32_t bLaneOff = (uint32_t)((warpCol * 64 + (lane & 7) + ((lane >> 4) << 3)) * ASTH
                                         + ((lane >> 3) & 1) * 8) * 2u;

    for (int kc = 0; kc < nk; kc++) {
        const int s = kc % 3;
        if (kc + 1 < nk) cp_wait1(); else cp_wait0();
        __syncthreads();
        if (kc + 2 < nk) {
            const uint32_t nb = smBase + (uint32_t)(((kc + 2) % 3) * STAGE_H) * 2u;
            stage_loads(A, Wt, M, K, rowBase, colBase, (kc + 2) * GBK,
                        nb, nb + GBM * ASTH * 2u, tid, aPack, shft, colOff);
        }

        const uint32_t aBase = smBase + (uint32_t)(s * STAGE_H) * 2u + aLaneOff;
        const uint32_t bBase = smBase + (uint32_t)(s * STAGE_H + GBM * ASTH) * 2u + bLaneOff;

        #pragma unroll
        for (int ks = 0; ks < 4; ks++) {
            const uint32_t ko = (uint32_t)ks * 32u;
            uint32_t afr[4][4], bfr[8][2];
            #pragma unroll
            for (int mt = 0; mt < 4; mt++)
                ldsm_x4(afr[mt], aBase + (uint32_t)(mt * 16 * ASTH) * 2u + ko);
            #pragma unroll
            for (int ntp = 0; ntp < 4; ntp++) {
                uint32_t q[4];
                ldsm_x4(q, bBase + (uint32_t)(ntp * 16 * ASTH) * 2u + ko);
                bfr[2 * ntp + 0][0] = q[0]; bfr[2 * ntp + 0][1] = q[1];
                bfr[2 * ntp + 1][0] = q[2]; bfr[2 * ntp + 1][1] = q[3];
            }
            #pragma unroll
            for (int mt = 0; mt < 4; mt++)
                #pragma unroll
                for (int nt = 0; nt < 8; nt++)
                    mma_f16(acc[mt][nt], afr[mt], bfr[nt]);
        }
    }

    // ---------------- epilogue ----------------
    float* Cf = (float*)Cv;
    __half* Ch = (__half*)Cv;
    #pragma unroll
    for (int mt = 0; mt < 4; mt++) {
        #pragma unroll
        for (int nt = 0; nt < 8; nt++) {
            const int r0 = rowBase + warpRow * 64 + mt * 16 + g;
            const int cc = colBase + warpCol * 64 + nt * 8 + 2 * tg;
            const float bx = bias[cc], by = bias[cc + 1];
            #pragma unroll
            for (int h = 0; h < 2; h++) {
                const int row = r0 + h * 8;
                if (row >= M) continue;
                float v0 = acc[mt][nt][2 * h + 0] + bx;
                float v1 = acc[mt][nt][2 * h + 1] + by;
                if (mode == 1) {
                    v0 = 0.5f * v0 * (1.0f + erff(v0 * 0.70710678118654752f));
                    v1 = 0.5f * v1 * (1.0f + erff(v1 * 0.70710678118654752f));
                    *(__half2*)(Ch + (size_t)row * N + cc) = __floats2half2_rn(v0, v1);
                } else if (mode == 3) {
                    *(__half2*)(Ch + (size_t)row * N + cc) = __floats2half2_rn(v0, v1);
                } else if (mode == 4) {
                    int b = row / TP_;
                    int r = row - b * TP_;
                    int t = r + shft; if (t >= TP_) t -= TP_;
                    if (t < T_)
                        *(__half2*)(Ch + ((size_t)b * T_ + t) * DIN_ + colOff + cc) =
                            __floats2half2_rn(v0, v1);
                } else {
                    if (mode == 2) {
                        const float2 rv = *(const float2*)(ga.res + (size_t)row * N + cc);
                        v0 += rv.x; v1 += rv.y;
                    }
                    *(float2*)(Cf + (size_t)row * N + cc) = make_float2(v0, v1);
                }
            }
        }
    }
}

// ---------------- fused prep: 8 weight transposes + x f2h ----
struct PrepArgs {
    const float* src[8];
    uint32_t     dstOff[8];
    int          K[8], N[8], tiles[8];
    const float* x;
    int          n8;
};
#define F2H_BLOCKS 16384

__global__ __launch_bounds__(256)
void prep_kernel(PrepArgs pa)
{
    const int tid = threadIdx.x;
    int bid = blockIdx.x;
    if (bid < F2H_BLOCKS) {
        __half* xh = g_xh;
        int idx = bid * 256 + tid;
        if (idx < pa.n8) {
            const float4* p = (const float4*)(pa.x + (size_t)idx * 8);
            float4 a = p[0], b = p[1];
            uint4 u;
            u.x = h2pack(a.x, a.y); u.y = h2pack(a.z, a.w);
            u.z = h2pack(b.x, b.y); u.w = h2pack(b.z, b.w);
            *(uint4*)(xh + (size_t)idx * 8) = u;
        }
        return;
    }
    bid -= F2H_BLOCKS;
    int e = 0;
    #pragma unroll
    for (int i = 0; i < 8; i++) {
        if (bid >= pa.tiles[i] && e == i) { bid -= pa.tiles[i]; e = i + 1; }
    }
    const float* src = pa.src[e];
    __half* dst = g_wt + pa.dstOff[e];
    const int K = pa.K[e], N = pa.N[e];
    const int tilesX = N >> 5;
    const int nb = (bid % tilesX) << 5;
    const int kb = (bid / tilesX) << 5;

    __shared__ float t[32][33];
    const int x = tid & 31, y = tid >> 5;
    #pragma unroll
    for (int i = 0; i < 32; i += 8)
        t[y + i][x] = src[(size_t)(kb + y + i) * N + nb + x];
    __syncthreads();
    #pragma unroll
    for (int i = 0; i < 32; i += 8)
        dst[(size_t)(nb + y + i) * K + kb + x] = __float2half(t[x][y + i]);
}

// ---------------- RMSNorm: fp32 in, fp16 out ----------------
__global__ void rmsnorm_kernel(const float* __restrict__ in, const float* __restrict__ w,
                               __half* __restrict__ out, int C)
{
    const int row = blockIdx.x;
    const float4* p4 = (const float4*)(in + (size_t)row * C);
    const float4* w4 = (const float4*)w;
    const int C4 = C >> 2;
    float s = 0.f;
    for (int c = threadIdx.x; c < C4; c += blockDim.x) {
        float4 v = p4[c];
        s += v.x * v.x + v.y * v.y + v.z * v.z + v.w * v.w;
    }
    #pragma unroll
    for (int o = 16; o > 0; o >>= 1) s += __shfl_xor_sync(0xffffffffu, s, o);
    __shared__ float red[8];
    __shared__ float scale;
    int wid = threadIdx.x >> 5, lane = threadIdx.x & 31;
    if (lane == 0) red[wid] = s;
    __syncthreads();
    if (threadIdx.x == 0) {
        float t = 0.f;
        for (int i = 0; i < (int)(blockDim.x >> 5); i++) t += red[i];
        scale = rsqrtf(t / (float)C + 1e-6f);
    }
    __syncthreads();
    float sc = scale;
    for (int c = threadIdx.x; c < C4; c += blockDim.x) {
        float4 v = p4[c], ww = w4[c];
        uint2 u;
        u.x = h2pack(v.x * sc * ww.x, v.y * sc * ww.y);
        u.y = h2pack(v.z * sc * ww.z, v.w * sc * ww.w);
        *(uint2*)(out + (size_t)row * C + c * 4) = u;
    }
}

// ---------------- windowed attention body (warp per b,window,head) ----------
template <int W, int NW, int SHIFT>
__device__ __forceinline__ void attn_body(
    const __half* __restrict__ qkv, __half* __restrict__ ao,
    const float* __restrict__ rpb, float* sm, int blk)
{
    constexpr int SLICE = 3 * W * 32 + W * W + 8;
    const int warp = threadIdx.x >> 5, lane = threadIdx.x & 31;
    float* S = sm + warp * SLICE;
    const int gw = blk * 4 + warp;
    const int h = gw & 7;
    const int n = (gw >> 3) % NW;
    const int b = gw / (8 * NW);

    float* q  = S;
    float* k  = S + W * 32;
    float* v  = S + 2 * W * 32;
    float* lg = S + 3 * W * 32;

    const size_t rbase = (size_t)b * TP_ + (size_t)n * W;
    #pragma unroll
    for (int i = 0; i < W; i++) {
        size_t ro = (rbase + i) * 768 + h * 32 + lane;
        q[i * 32 + lane] = __half2float(qkv[ro]);
        k[i * 32 + lane] = __half2float(qkv[ro + 256]);
        v[i * 32 + lane] = __half2float(qkv[ro + 512]);
    }
    __syncwarp();

    const float scale = 0.17677669529663687f;
    const bool lastwin = (n == NW - 1);
    for (int p = lane; p < W * W; p += 32) {
        int i = p / W, j = p % W;
        float s = 0.f;
        #pragma unroll
        for (int d = 0; d < 32; d++) s = fmaf(q[i * 32 + d], k[j * 32 + d], s);
        s *= scale;
        s += rpb[(i - j + W - 1) * 8 + h];
        if (lastwin) {
            int mi = (i >= W - SHIFT) ? 2 : 1;
            int mj = (j >= W - SHIFT) ? 2 : 1;
            if (mi != mj) s -= 100.f;
        }
        lg[p] = s;
    }
    __syncwarp();

    if (lane < W) {
        float mx = -3.0e38f;
        #pragma unroll
        for (int j = 0; j < W; j++) mx = fmaxf(mx, lg[lane * W + j]);
        float sum = 0.f;
        #pragma unroll
        for (int j = 0; j < W; j++) {
            float e = __expf(lg[lane * W + j] - mx);
            lg[lane * W + j] = e; sum += e;
        }
        float inv = 1.f / sum;
        #pragma unroll
        for (int j = 0; j < W; j++) lg[lane * W + j] *= inv;
    }
    __syncwarp();

    #pragma unroll
    for (int i = 0; i < W; i++) {
        float a = 0.f;
        #pragma unroll
        for (int j = 0; j < W; j++) a = fmaf(lg[i * W + j], v[j * 32 + lane], a);
        ao[(rbase + i) * 256 + h * 32 + lane] = __float2half(a);
    }
}

// merged: branch1 blocks [0, N1B), branch2 blocks [N1B, N1B+N2B)
#define ATT_N1B (B_ * NW1_ * HBR_ / 4)     // 6560
#define ATT_N2B (B_ * NW2_ * HBR_ / 4)     // 3280
#define ATT_SLICE_MAX (3 * 20 * 32 + 20 * 20 + 8)   // 2328

__global__ __launch_bounds__(128)
void attn_merged(const __half* __restrict__ qkv1, __half* __restrict__ ao1,
                 const float* __restrict__ rpb1,
                 const __half* __restrict__ qkv2, __half* __restrict__ ao2,
                 const float* __restrict__ rpb2)
{
    __shared__ float sm[4 * ATT_SLICE_MAX];
    if (blockIdx.x < ATT_N1B)
        attn_body<10, NW1_, 5>(qkv1, ao1, rpb1, sm, blockIdx.x);
    else
        attn_body<20, NW2_, 10>(qkv2, ao2, rpb2, sm, blockIdx.x - ATT_N1B);
}

// ---------------- launch ----------------
extern "C" void kernel_launch(void* const* d_in, const int* in_sizes, int n_in,
                              void* d_out, int out_size)
{
    (void)in_sizes; (void)n_in; (void)out_size;
    const float* x       = (const float*)d_in[0];
    const float* down_w  = (const float*)d_in[1];
    const float* down_b  = (const float*)d_in[2];
    const float* up_w    = (const float*)d_in[3];
    const float* up_b    = (const float*)d_in[4];
    const float* n1w     = (const float*)d_in[5];
    const float* n2w     = (const float*)d_in[6];
    const float* qkv1_w  = (const float*)d_in[7];
    const float* qkv1_b  = (const float*)d_in[8];
    const float* proj1_w = (const float*)d_in[9];
    const float* proj1_b = (const float*)d_in[10];
    const float* rpb1    = (const float*)d_in[11];
    const float* qkv2_w  = (const float*)d_in[12];
    const float* qkv2_b  = (const float*)d_in[13];
    const float* proj2_w = (const float*)d_in[14];
    const float* proj2_b = (const float*)d_in[15];
    const float* rpb2    = (const float*)d_in[16];
    const float* ffn_w1  = (const float*)d_in[17];
    const float* ffn_b1  = (const float*)d_in[18];
    const float* ffn_w2  = (const float*)d_in[19];
    const float* ffn_b2  = (const float*)d_in[20];
    float* out = (float*)d_out;

    __half *xh, *xih, *qk1, *qk2, *ao1, *ao2, *xcat, *hbuf, *ffn, *wt;
    float *xi, *xmid;
    cudaGetSymbolAddress((void**)&xh,   g_xh);
    cudaGetSymbolAddress((void**)&xi,   g_xi);
    cudaGetSymbolAddress((void**)&xih,  g_xih);
    cudaGetSymbolAddress((void**)&qk1,  g_qkv1);
    cudaGetSymbolAddress((void**)&qk2,  g_qkv2);
    cudaGetSymbolAddress((void**)&ao1,  g_ao1);
    cudaGetSymbolAddress((void**)&ao2,  g_ao2);
    cudaGetSymbolAddress((void**)&xcat, g_xcat);
    cudaGetSymbolAddress((void**)&xmid, g_xmid);
    cudaGetSymbolAddress((void**)&hbuf, g_h);
    cudaGetSymbolAddress((void**)&ffn,  g_ffn);
    cudaGetSymbolAddress((void**)&wt,   g_wt);

    cudaFuncSetAttribute(mma_gemm, cudaFuncAttributeMaxDynamicSharedMemorySize, GEMM_SMEM);

    const int MT = B_ * T_;    // 32768
    const int MP = B_ * TP_;   // 32800
    const int MT_TILES = MT / GBM;              // 256
    const int MP_TILES = (MP + GBM - 1) / GBM;  // 257

    // 0. fused prep
    PrepArgs pa;
    const float* srcs[8]  = { down_w, up_w, qkv1_w, qkv2_w, proj1_w, proj2_w, ffn_w1, ffn_w2 };
    const uint32_t offs[8] = { O_DOWN, O_UP, O_QKV1, O_QKV2, O_PROJ1, O_PROJ2, O_FFN1, O_FFN2 };
    const int Ks[8] = { DIM_, DIN_, DBR_, DBR_, DBR_, DBR_, DIM_, 2*DIM_ };
    const int Ns[8] = { DIN_, DIM_, 768,  768,  DBR_, DBR_, 2*DIM_, DIM_ };
    int totalTiles = 0;
    for (int i = 0; i < 8; i++) {
        pa.src[i] = srcs[i]; pa.dstOff[i] = offs[i];
        pa.K[i] = Ks[i]; pa.N[i] = Ns[i];
        pa.tiles[i] = (Ns[i] / 32) * (Ks[i] / 32);
        totalTiles += pa.tiles[i];
    }
    pa.x = x; pa.n8 = MT * DIM_ / 8;
    prep_kernel<<<F2H_BLOCKS + totalTiles, 256>>>(pa);

    auto single = [&](const __half* A, const __half* Wt_, const float* b,
                      const float* r, void* C) {
        GemmArgs ga;
        ga.A[0] = ga.A[1] = A; ga.Wt[0] = ga.Wt[1] = Wt_;
        ga.bias[0] = ga.bias[1] = b; ga.res = r;
        ga.C[0] = ga.C[1] = C;
        ga.shift[0] = ga.shift[1] = 0; ga.colOff[0] = ga.colOff[1] = 0;
        return ga;
    };

    // 1. down + rmsnorm1
    mma_gemm<<<dim3(DIN_/GBN, MT_TILES, 1), 256, GEMM_SMEM>>>(
        single(xh, wt + O_DOWN, down_b, nullptr, xi), MT, DIN_, DIM_, 0, 0);
    rmsnorm_kernel<<<MT, 128>>>(xi, n1w, xih, DIN_);

    // 2. QKV both branches, one launch (fused pack)
    {
        GemmArgs ga;
        ga.A[0] = ga.A[1] = xih;
        ga.Wt[0] = wt + O_QKV1; ga.Wt[1] = wt + O_QKV2;
        ga.bias[0] = qkv1_b;    ga.bias[1] = qkv2_b;
        ga.res = nullptr;
        ga.C[0] = qk1;          ga.C[1] = qk2;
        ga.shift[0] = 5;        ga.shift[1] = 10;
        ga.colOff[0] = 0;       ga.colOff[1] = DBR_;
        mma_gemm<<<dim3(768/GBN, MP_TILES, 2), 256, GEMM_SMEM>>>(
            ga, MP, 768, DBR_, 3, 1);
    }

    // 3. attention, both branches in one launch
    attn_merged<<<ATT_N1B + ATT_N2B, 128>>>(qk1, ao1, rpb1, qk2, ao2, rpb2);

    // 4. proj both branches, one launch (fused unshift into xcat)
    {
        GemmArgs ga;
        ga.A[0] = ao1;          ga.A[1] = ao2;
        ga.Wt[0] = wt + O_PROJ1; ga.Wt[1] = wt + O_PROJ2;
        ga.bias[0] = proj1_b;   ga.bias[1] = proj2_b;
        ga.res = nullptr;
        ga.C[0] = ga.C[1] = xcat;
        ga.shift[0] = 5;        ga.shift[1] = 10;
        ga.colOff[0] = 0;       ga.colOff[1] = DBR_;
        mma_gemm<<<dim3(DBR_/GBN, MP_TILES, 2), 256, GEMM_SMEM>>>(
            ga, MP, DBR_, DBR_, 4, 0);
    }

    // 5. up + residual
    mma_gemm<<<dim3(DIM_/GBN, MT_TILES, 1), 256, GEMM_SMEM>>>(
        single(xcat, wt + O_UP, up_b, x, xmid), MT, DIM_, DIN_, 2, 0);

    // 6. rmsnorm2
    rmsnorm_kernel<<<MT, 256>>>(xmid, n2w, hbuf, DIM_);

    // 7. FFN1 + GELU
    mma_gemm<<<dim3(2*DIM_/GBN, MT_TILES, 1), 256, GEMM_SMEM>>>(
        single(hbuf, wt + O_FFN1, ffn_b1, nullptr, ffn), MT, 2*DIM_, DIM_, 1, 0);

    // 8. FFN2 + residual -> out
    mma_gemm<<<dim3(DIM_/GBN, MT_TILES, 1), 256, GEMM_SMEM>>>(
        single(ffn, wt + O_FFN2, ffn_b2, xmid, out), MT, DIM_, 2*DIM_, 2, 0);
}

// round 14
// speedup vs baseline: 1.1213x; 1.1213x over previous
#include <cuda_runtime.h>
#include <cuda_fp16.h>
#include <math.h>
#include <stdint.h>

// ---------------- problem constants ----------------
#define B_    8
#define T_    4096
#define DIM_  1024
#define DIN_  512
#define DBR_  256
#define HBR_  8
#define TP_   4100
#define NW1_  410
#define NW2_  205

// ---------------- device scratch (static) ----------------
__device__ __half g_xh  [B_*T_*DIM_];
__device__ float  g_xi  [B_*T_*DIN_];
__device__ __half g_xih [B_*T_*DIN_];
__device__ __half g_qkv1[B_*TP_*3*DBR_];
__device__ __half g_qkv2[B_*TP_*3*DBR_];
__device__ __half g_ao1 [B_*TP_*DBR_];
__device__ __half g_ao2 [B_*TP_*DBR_];
__device__ __half g_xcat[B_*T_*DIN_];
__device__ float  g_xmid[B_*T_*DIM_];
__device__ __half g_h   [B_*T_*DIM_];
__device__ __half g_ffn [B_*T_*2*DIM_];
__device__ __half g_wt  [5767168];

#define O_DOWN  0u
#define O_UP    524288u
#define O_QKV1  1048576u
#define O_QKV2  1245184u
#define O_PROJ1 1441792u
#define O_PROJ2 1507328u
#define O_FFN1  1572864u
#define O_FFN2  3670016u

// ---------------- PTX helpers ----------
__device__ __forceinline__ uint32_t smem_u32(const void* p) {
    uint32_t a;
    asm("{ .reg .u64 t; cvta.to.shared.u64 t, %1; cvt.u32.u64 %0, t; }" : "=r"(a) : "l"(p));
    return a;
}
__device__ __forceinline__ uint32_t h2pack(float lo, float hi) {
    __half2 h = __floats2half2_rn(lo, hi);
    return *reinterpret_cast<uint32_t*>(&h);
}
__device__ __forceinline__ void mma_f16(float* d, const uint32_t* a, const uint32_t* b) {
    asm volatile(
        "mma.sync.aligned.m16n8k16.row.col.f32.f16.f16.f32 "
        "{%0,%1,%2,%3}, {%4,%5,%6,%7}, {%8,%9}, {%0,%1,%2,%3};"
        : "+f"(d[0]), "+f"(d[1]), "+f"(d[2]), "+f"(d[3])
        : "r"(a[0]), "r"(a[1]), "r"(a[2]), "r"(a[3]), "r"(b[0]), "r"(b[1]));
}
__device__ __forceinline__ void ldsm_x4(uint32_t* r, uint32_t addr) {
    asm volatile("ldmatrix.sync.aligned.m8n8.x4.shared.b16 {%0,%1,%2,%3}, [%4];"
                 : "=r"(r[0]), "=r"(r[1]), "=r"(r[2]), "=r"(r[3]) : "r"(addr));
}
__device__ __forceinline__ void cp_async16(uint32_t dst, const void* src, int szBytes) {
    asm volatile("cp.async.cg.shared.global [%0], [%1], 16, %2;"
                 :: "r"(dst), "l"(src), "r"(szBytes));
}
__device__ __forceinline__ void cp_async16f(uint32_t dst, const void* src) {
    asm volatile("cp.async.cg.shared.global [%0], [%1], 16;"
                 :: "r"(dst), "l"(src));
}
__device__ __forceinline__ void cp_commit() { asm volatile("cp.async.commit_group;" ::: "memory"); }
__device__ __forceinline__ void cp_wait1()  { asm volatile("cp.async.wait_group 1;" ::: "memory"); }
__device__ __forceinline__ void cp_wait0()  { asm volatile("cp.async.wait_group 0;" ::: "memory"); }

// ---------------- fp16-storage warp-mma GEMM (fp32 accumulate) ----------------
// C[M,N] = A[M,K] @ Wt[N,K]^T + bias
// mode 0: bias, fp32 out           mode 1: bias+GELU, fp16 out
// mode 2: bias+res, fp32 out       mode 3: bias, fp16 out
// mode 4: bias, fp16 out with unshift row-remap into [B*T, DIN] at col oColOff
// aPack: A rows gathered from [B*T_, DIN_] via roll(+aShift)+pad, col offset aColOff
#define GBM 128
#define GBN 256
#define GBK 64
#define ASTH 72
#define STAGE_H ((GBM + GBN) * ASTH)
#define GEMM_SMEM (3 * STAGE_H * 2)             // 165888 bytes

__device__ __forceinline__ void stage_loads(
    const __half* __restrict__ A, const __half* __restrict__ Wt,
    int M, int K, int rowBase, int colBase, int k0,
    uint32_t asBase, uint32_t bsBase, int tid,
    int aPack, int aShift, int aColOff)
{
    #pragma unroll
    for (int i = 0; i < 4; i++) {
        int idx = tid + i * 256;
        int r = idx >> 3, c = (idx & 7) << 3;
        int gr = rowBase + r;
        const __half* src;
        int sz;
        if (aPack) {
            int b = gr / TP_;
            int t = gr - b * TP_;
            int ts = t + aShift; if (ts >= TP_) ts -= TP_;
            sz = (gr < M && ts < T_) ? 16 : 0;
            if (ts >= T_) ts = 0;
            if (b >= B_) b = B_ - 1;
            src = A + ((size_t)b * T_ + ts) * DIN_ + aColOff + k0 + c;
        } else {
            sz = (gr < M) ? 16 : 0;
            if (gr >= M) gr = M - 1;
            src = A + (size_t)gr * K + k0 + c;
        }
        cp_async16(asBase + (uint32_t)(r * ASTH + c) * 2u, src, sz);
    }
    #pragma unroll
    for (int i = 0; i < 8; i++) {
        int idx = tid + i * 256;
        int r = idx >> 3, c = (idx & 7) << 3;
        cp_async16f(bsBase + (uint32_t)(r * ASTH + c) * 2u,
                    Wt + (size_t)(colBase + r) * K + k0 + c);
    }
    cp_commit();
}

__global__ __launch_bounds__(256, 1)
void mma_gemm(const __half* __restrict__ A, const __half* __restrict__ Wt,
              const float* __restrict__ bias, const float* __restrict__ res,
              void* __restrict__ Cv, int M, int N, int K, int mode,
              int aPack, int aShift, int aColOff, int oShift, int oColOff)
{
    extern __shared__ __half smh[];
    const uint32_t smBase = smem_u32(smh);

    const int tid  = threadIdx.x;
    const int wid  = tid >> 5;
    const int lane = tid & 31;
    const int g    = lane >> 2;
    const int tg   = lane & 3;
    const int warpRow = wid >> 2;
    const int warpCol = wid & 3;
    const int rowBase = blockIdx.y * GBM;
    const int colBase = blockIdx.x * GBN;

    float acc[4][8][4];
    #pragma unroll
    for (int mt = 0; mt < 4; mt++)
        #pragma unroll
        for (int nt = 0; nt < 8; nt++)
            #pragma unroll
            for (int i = 0; i < 4; i++) acc[mt][nt][i] = 0.f;

    const int nk = K >> 6;
    stage_loads(A, Wt, M, K, rowBase, colBase, 0,
                smBase, smBase + GBM * ASTH * 2u, tid, aPack, aShift, aColOff);
    if (nk > 1) {
        const uint32_t b1 = smBase + (uint32_t)STAGE_H * 2u;
        stage_loads(A, Wt, M, K, rowBase, colBase, GBK,
                    b1, b1 + GBM * ASTH * 2u, tid, aPack, aShift, aColOff);
    }

    const uint32_t aLaneOff = (uint32_t)((warpRow * 64 + (lane & 15)) * ASTH + (lane >> 4) * 8) * 2u;
    const uint32_t bLaneOff = (uint32_t)((warpCol * 64 + (lane & 7) + ((lane >> 4) << 3)) * ASTH
                                         + ((lane >> 3) & 1) * 8) * 2u;

    for (int kc = 0; kc < nk; kc++) {
        const int s = kc % 3;
        if (kc + 1 < nk) cp_wait1(); else cp_wait0();
        __syncthreads();
        // issue loads for stage kc+2 AFTER the barrier: its target buffer
        // ((kc+2)%3 == (kc-1)%3) was last read in iteration kc-1, which every
        // warp finished before this barrier.
        if (kc + 2 < nk) {
            const uint32_t nb = smBase + (uint32_t)(((kc + 2) % 3) * STAGE_H) * 2u;
            stage_loads(A, Wt, M, K, rowBase, colBase, (kc + 2) * GBK,
                        nb, nb + GBM * ASTH * 2u, tid, aPack, aShift, aColOff);
        }

        const uint32_t aBase = smBase + (uint32_t)(s * STAGE_H) * 2u + aLaneOff;
        const uint32_t bBase = smBase + (uint32_t)(s * STAGE_H + GBM * ASTH) * 2u + bLaneOff;

        #pragma unroll
        for (int ks = 0; ks < 4; ks++) {
            const uint32_t ko = (uint32_t)ks * 32u;
            uint32_t afr[4][4], bfr[8][2];
            #pragma unroll
            for (int mt = 0; mt < 4; mt++)
                ldsm_x4(afr[mt], aBase + (uint32_t)(mt * 16 * ASTH) * 2u + ko);
            #pragma unroll
            for (int ntp = 0; ntp < 4; ntp++) {
                uint32_t q[4];
                ldsm_x4(q, bBase + (uint32_t)(ntp * 16 * ASTH) * 2u + ko);
                bfr[2 * ntp + 0][0] = q[0]; bfr[2 * ntp + 0][1] = q[1];
                bfr[2 * ntp + 1][0] = q[2]; bfr[2 * ntp + 1][1] = q[3];
            }
            #pragma unroll
            for (int mt = 0; mt < 4; mt++)
                #pragma unroll
                for (int nt = 0; nt < 8; nt++)
                    mma_f16(acc[mt][nt], afr[mt], bfr[nt]);
        }
    }

    // ---------------- epilogue ----------------
    float* Cf = (float*)Cv;
    __half* Ch = (__half*)Cv;
    #pragma unroll
    for (int mt = 0; mt < 4; mt++) {
        #pragma unroll
        for (int nt = 0; nt < 8; nt++) {
            const int r0 = rowBase + warpRow * 64 + mt * 16 + g;
            const int cc = colBase + warpCol * 64 + nt * 8 + 2 * tg;
            const float bx = bias[cc], by = bias[cc + 1];
            #pragma unroll
            for (int h = 0; h < 2; h++) {
                const int row = r0 + h * 8;
                if (row >= M) continue;
                float v0 = acc[mt][nt][2 * h + 0] + bx;
                float v1 = acc[mt][nt][2 * h + 1] + by;
                if (mode == 1) {
                    v0 = 0.5f * v0 * (1.0f + erff(v0 * 0.70710678118654752f));
                    v1 = 0.5f * v1 * (1.0f + erff(v1 * 0.70710678118654752f));
                    *(__half2*)(Ch + (size_t)row * N + cc) = __floats2half2_rn(v0, v1);
                } else if (mode == 3) {
                    *(__half2*)(Ch + (size_t)row * N + cc) = __floats2half2_rn(v0, v1);
                } else if (mode == 4) {
                    int b = row / TP_;
                    int r = row - b * TP_;
                    int t = r + oShift; if (t >= TP_) t -= TP_;
                    if (t < T_)
                        *(__half2*)(Ch + ((size_t)b * T_ + t) * DIN_ + oColOff + cc) =
                            __floats2half2_rn(v0, v1);
                } else {
                    if (mode == 2) {
                        const float2 rv = *(const float2*)(res + (size_t)row * N + cc);
                        v0 += rv.x; v1 += rv.y;
                    }
                    *(float2*)(Cf + (size_t)row * N + cc) = make_float2(v0, v1);
                }
            }
        }
    }
}

// ---------------- fused prep: 8 weight transposes + x f2h ----
struct PrepArgs {
    const float* src[8];
    uint32_t     dstOff[8];
    int          K[8], N[8], tiles[8];
    const float* x;
    int          n8;
};
#define F2H_BLOCKS 16384

__global__ __launch_bounds__(256)
void prep_kernel(PrepArgs pa)
{
    const int tid = threadIdx.x;
    int bid = blockIdx.x;
    if (bid < F2H_BLOCKS) {
        __half* xh = g_xh;
        int idx = bid * 256 + tid;
        if (idx < pa.n8) {
            const float4* p = (const float4*)(pa.x + (size_t)idx * 8);
            float4 a = p[0], b = p[1];
            uint4 u;
            u.x = h2pack(a.x, a.y); u.y = h2pack(a.z, a.w);
            u.z = h2pack(b.x, b.y); u.w = h2pack(b.z, b.w);
            *(uint4*)(xh + (size_t)idx * 8) = u;
        }
        return;
    }
    bid -= F2H_BLOCKS;
    int e = 0;
    #pragma unroll
    for (int i = 0; i < 8; i++) {
        if (bid >= pa.tiles[i] && e == i) { bid -= pa.tiles[i]; e = i + 1; }
    }
    const float* src = pa.src[e];
    __half* dst = g_wt + pa.dstOff[e];
    const int K = pa.K[e], N = pa.N[e];
    const int tilesX = N >> 5;
    const int nb = (bid % tilesX) << 5;
    const int kb = (bid / tilesX) << 5;

    __shared__ float t[32][33];
    const int x = tid & 31, y = tid >> 5;
    #pragma unroll
    for (int i = 0; i < 32; i += 8)
        t[y + i][x] = src[(size_t)(kb + y + i) * N + nb + x];
    __syncthreads();
    #pragma unroll
    for (int i = 0; i < 32; i += 8)
        dst[(size_t)(nb + y + i) * K + kb + x] = __float2half(t[x][y + i]);
}

// ---------------- RMSNorm: fp32 in, fp16 out ----------------
__global__ void rmsnorm_kernel(const float* __restrict__ in, const float* __restrict__ w,
                               __half* __restrict__ out, int C)
{
    const int row = blockIdx.x;
    const float4* p4 = (const float4*)(in + (size_t)row * C);
    const float4* w4 = (const float4*)w;
    const int C4 = C >> 2;
    float s = 0.f;
    for (int c = threadIdx.x; c < C4; c += blockDim.x) {
        float4 v = p4[c];
        s += v.x * v.x + v.y * v.y + v.z * v.z + v.w * v.w;
    }
    #pragma unroll
    for (int o = 16; o > 0; o >>= 1) s += __shfl_xor_sync(0xffffffffu, s, o);
    __shared__ float red[8];
    __shared__ float scale;
    int wid = threadIdx.x >> 5, lane = threadIdx.x & 31;
    if (lane == 0) red[wid] = s;
    __syncthreads();
    if (threadIdx.x == 0) {
        float t = 0.f;
        for (int i = 0; i < (int)(blockDim.x >> 5); i++) t += red[i];
        scale = rsqrtf(t / (float)C + 1e-6f);
    }
    __syncthreads();
    float sc = scale;
    for (int c = threadIdx.x; c < C4; c += blockDim.x) {
        float4 v = p4[c], ww = w4[c];
        uint2 u;
        u.x = h2pack(v.x * sc * ww.x, v.y * sc * ww.y);
        u.y = h2pack(v.z * sc * ww.z, v.w * sc * ww.w);
        *(uint2*)(out + (size_t)row * C + c * 4) = u;
    }
}

// ---------------- windowed attention, templated (warp per b,window,head) ----------
template <int W, int NW, int SHIFT>
__global__ __launch_bounds__(128)
void attn_kernel(const __half* __restrict__ qkv, __half* __restrict__ ao,
                 const float* __restrict__ rpb)
{
    constexpr int SLICE = 3 * W * 32 + W * W + 8;
    __shared__ float sm[4 * SLICE];
    const int warp = threadIdx.x >> 5, lane = threadIdx.x & 31;
    float* S = sm + warp * SLICE;
    const int gw = blockIdx.x * 4 + warp;
    const int h = gw & 7;
    const int n = (gw >> 3) % NW;
    const int b = gw / (8 * NW);

    float* q  = S;
    float* k  = S + W * 32;
    float* v  = S + 2 * W * 32;
    float* lg = S + 3 * W * 32;

    const size_t rbase = (size_t)b * TP_ + (size_t)n * W;
    #pragma unroll
    for (int i = 0; i < W; i++) {
        size_t ro = (rbase + i) * 768 + h * 32 + lane;
        q[i * 32 + lane] = __half2float(qkv[ro]);
        k[i * 32 + lane] = __half2float(qkv[ro + 256]);
        v[i * 32 + lane] = __half2float(qkv[ro + 512]);
    }
    __syncwarp();

    const float scale = 0.17677669529663687f;
    const bool lastwin = (n == NW - 1);
    for (int p = lane; p < W * W; p += 32) {
        int i = p / W, j = p % W;
        float s = 0.f;
        #pragma unroll
        for (int d = 0; d < 32; d++) s = fmaf(q[i * 32 + d], k[j * 32 + d], s);
        s *= scale;
        s += rpb[(i - j + W - 1) * 8 + h];
        if (lastwin) {
            int mi = (i >= W - SHIFT) ? 2 : 1;
            int mj = (j >= W - SHIFT) ? 2 : 1;
            if (mi != mj) s -= 100.f;
        }
        lg[p] = s;
    }
    __syncwarp();

    if (lane < W) {
        float mx = -3.0e38f;
        #pragma unroll
        for (int j = 0; j < W; j++) mx = fmaxf(mx, lg[lane * W + j]);
        float sum = 0.f;
        #pragma unroll
        for (int j = 0; j < W; j++) {
            float e = __expf(lg[lane * W + j] - mx);
            lg[lane * W + j] = e; sum += e;
        }
        float inv = 1.f / sum;
        #pragma unroll
        for (int j = 0; j < W; j++) lg[lane * W + j] *= inv;
    }
    __syncwarp();

    #pragma unroll
    for (int i = 0; i < W; i++) {
        float a = 0.f;
        #pragma unroll
        for (int j = 0; j < W; j++) a = fmaf(lg[i * W + j], v[j * 32 + lane], a);
        ao[(rbase + i) * 256 + h * 32 + lane] = __float2half(a);
    }
}

// ---------------- launch ----------------
extern "C" void kernel_launch(void* const* d_in, const int* in_sizes, int n_in,
                              void* d_out, int out_size)
{
    (void)in_sizes; (void)n_in; (void)out_size;
    const float* x       = (const float*)d_in[0];
    const float* down_w  = (const float*)d_in[1];
    const float* down_b  = (const float*)d_in[2];
    const float* up_w    = (const float*)d_in[3];
    const float* up_b    = (const float*)d_in[4];
    const float* n1w     = (const float*)d_in[5];
    const float* n2w     = (const float*)d_in[6];
    const float* qkv1_w  = (const float*)d_in[7];
    const float* qkv1_b  = (const float*)d_in[8];
    const float* proj1_w = (const float*)d_in[9];
    const float* proj1_b = (const float*)d_in[10];
    const float* rpb1    = (const float*)d_in[11];
    const float* qkv2_w  = (const float*)d_in[12];
    const float* qkv2_b  = (const float*)d_in[13];
    const float* proj2_w = (const float*)d_in[14];
    const float* proj2_b = (const float*)d_in[15];
    const float* rpb2    = (const float*)d_in[16];
    const float* ffn_w1  = (const float*)d_in[17];
    const float* ffn_b1  = (const float*)d_in[18];
    const float* ffn_w2  = (const float*)d_in[19];
    const float* ffn_b2  = (const float*)d_in[20];
    float* out = (float*)d_out;

    __half *xh, *xih, *qk1, *qk2, *ao1, *ao2, *xcat, *hbuf, *ffn, *wt;
    float *xi, *xmid;
    cudaGetSymbolAddress((void**)&xh,   g_xh);
    cudaGetSymbolAddress((void**)&xi,   g_xi);
    cudaGetSymbolAddress((void**)&xih,  g_xih);
    cudaGetSymbolAddress((void**)&qk1,  g_qkv1);
    cudaGetSymbolAddress((void**)&qk2,  g_qkv2);
    cudaGetSymbolAddress((void**)&ao1,  g_ao1);
    cudaGetSymbolAddress((void**)&ao2,  g_ao2);
    cudaGetSymbolAddress((void**)&xcat, g_xcat);
    cudaGetSymbolAddress((void**)&xmid, g_xmid);
    cudaGetSymbolAddress((void**)&hbuf, g_h);
    cudaGetSymbolAddress((void**)&ffn,  g_ffn);
    cudaGetSymbolAddress((void**)&wt,   g_wt);

    cudaFuncSetAttribute(mma_gemm, cudaFuncAttributeMaxDynamicSharedMemorySize, GEMM_SMEM);

    const int MT = B_ * T_;    // 32768
    const int MP = B_ * TP_;   // 32800
    const int MT_TILES = MT / GBM;              // 256
    const int MP_TILES = (MP + GBM - 1) / GBM;  // 257

    // 0. fused prep: all transposes + f2h (one launch)
    PrepArgs pa;
    const float* srcs[8]  = { down_w, up_w, qkv1_w, qkv2_w, proj1_w, proj2_w, ffn_w1, ffn_w2 };
    const uint32_t offs[8] = { O_DOWN, O_UP, O_QKV1, O_QKV2, O_PROJ1, O_PROJ2, O_FFN1, O_FFN2 };
    const int Ks[8] = { DIM_, DIN_, DBR_, DBR_, DBR_, DBR_, DIM_, 2*DIM_ };
    const int Ns[8] = { DIN_, DIM_, 768,  768,  DBR_, DBR_, 2*DIM_, DIM_ };
    int totalTiles = 0;
    for (int i = 0; i < 8; i++) {
        pa.src[i] = srcs[i]; pa.dstOff[i] = offs[i];
        pa.K[i] = Ks[i]; pa.N[i] = Ns[i];
        pa.tiles[i] = (Ns[i] / 32) * (Ks[i] / 32);
        totalTiles += pa.tiles[i];
    }
    pa.x = x; pa.n8 = MT * DIM_ / 8;
    prep_kernel<<<F2H_BLOCKS + totalTiles, 256>>>(pa);

    // 1. down + rmsnorm1 (fp16 out)
    mma_gemm<<<dim3(DIN_/GBN, MT_TILES), 256, GEMM_SMEM>>>(
        xh, wt + O_DOWN, down_b, nullptr, xi, MT, DIN_, DIM_, 0, 0, 0, 0, 0, 0);
    rmsnorm_kernel<<<MT, 128>>>(xi, n1w, xih, DIN_);

    // 2. QKV with fused pack (A gathered from xih with roll)
    mma_gemm<<<dim3(768/GBN, MP_TILES), 256, GEMM_SMEM>>>(
        xih, wt + O_QKV1, qkv1_b, nullptr, qk1, MP, 768, DBR_, 3, 1, 5, 0, 0, 0);
    mma_gemm<<<dim3(768/GBN, MP_TILES), 256, GEMM_SMEM>>>(
        xih, wt + O_QKV2, qkv2_b, nullptr, qk2, MP, 768, DBR_, 3, 1, 10, DBR_, 0, 0);

    // 3. attention (templated, per-W smem sizing)
    attn_kernel<10, NW1_, 5><<<B_ * NW1_ * HBR_ / 4, 128>>>(qk1, ao1, rpb1);
    attn_kernel<20, NW2_, 10><<<B_ * NW2_ * HBR_ / 4, 128>>>(qk2, ao2, rpb2);

    // 4. proj with fused unshift epilogue (writes into xcat)
    mma_gemm<<<dim3(DBR_/GBN, MP_TILES), 256, GEMM_SMEM>>>(
        ao1, wt + O_PROJ1, proj1_b, nullptr, xcat, MP, DBR_, DBR_, 4, 0, 0, 0, 5, 0);
    mma_gemm<<<dim3(DBR_/GBN, MP_TILES), 256, GEMM_SMEM>>>(
        ao2, wt + O_PROJ2, proj2_b, nullptr, xcat, MP, DBR_, DBR_, 4, 0, 0, 0, 10, DBR_);

    // 5. up + residual (fp32 out)
    mma_gemm<<<dim3(DIM_/GBN, MT_TILES), 256, GEMM_SMEM>>>(
        xcat, wt + O_UP, up_b, x, xmid, MT, DIM_, DIN_, 2, 0, 0, 0, 0, 0);

    // 6. rmsnorm2 (fp16 out)
    rmsnorm_kernel<<<MT, 256>>>(xmid, n2w, hbuf, DIM_);

    // 7. FFN1 + GELU (fp16 out)
    mma_gemm<<<dim3(2*DIM_/GBN, MT_TILES), 256, GEMM_SMEM>>>(
        hbuf, wt + O_FFN1, ffn_b1, nullptr, ffn, MT, 2*DIM_, DIM_, 1, 0, 0, 0, 0, 0);

    // 8. FFN2 + residual -> out (fp32)
    mma_gemm<<<dim3(DIM_/GBN, MT_TILES), 256, GEMM_SMEM>>>(
        ffn, wt + O_FFN2, ffn_b2, xmid, out, MT, DIM_, 2*DIM_, 2, 0, 0, 0, 0, 0);
}

// round 15
// speedup vs baseline: 1.1417x; 1.0182x over previous
#include <cuda_runtime.h>
#include <cuda_fp16.h>
#include <math.h>
#include <stdint.h>

// ---------------- problem constants ----------------
#define B_    8
#define T_    4096
#define DIM_  1024
#define DIN_  512
#define DBR_  256
#define HBR_  8
#define TP_   4100
#define NW1_  410
#define NW2_  205

// ---------------- device scratch (static) ----------------
__device__ __half g_xh  [B_*T_*DIM_];
__device__ float  g_xi  [B_*T_*DIN_];
__device__ __half g_xih [B_*T_*DIN_];
__device__ __half g_qkv1[B_*TP_*3*DBR_];
__device__ __half g_qkv2[B_*TP_*3*DBR_];
__device__ __half g_ao1 [B_*TP_*DBR_];
__device__ __half g_ao2 [B_*TP_*DBR_];
__device__ __half g_xcat[B_*T_*DIN_];
__device__ float  g_xmid[B_*T_*DIM_];
__device__ __half g_h   [B_*T_*DIM_];
__device__ __half g_ffn [B_*T_*2*DIM_];
__device__ __half g_wt  [5767168];

#define O_DOWN  0u
#define O_UP    524288u
#define O_QKV1  1048576u
#define O_QKV2  1245184u
#define O_PROJ1 1441792u
#define O_PROJ2 1507328u
#define O_FFN1  1572864u
#define O_FFN2  3670016u

// ---------------- PTX helpers ----------
__device__ __forceinline__ uint32_t smem_u32(const void* p) {
    uint32_t a;
    asm("{ .reg .u64 t; cvta.to.shared.u64 t, %1; cvt.u32.u64 %0, t; }" : "=r"(a) : "l"(p));
    return a;
}
__device__ __forceinline__ uint32_t h2pack(float lo, float hi) {
    __half2 h = __floats2half2_rn(lo, hi);
    return *reinterpret_cast<uint32_t*>(&h);
}
__device__ __forceinline__ void mma_f16(float* d, const uint32_t* a, const uint32_t* b) {
    asm volatile(
        "mma.sync.aligned.m16n8k16.row.col.f32.f16.f16.f32 "
        "{%0,%1,%2,%3}, {%4,%5,%6,%7}, {%8,%9}, {%0,%1,%2,%3};"
        : "+f"(d[0]), "+f"(d[1]), "+f"(d[2]), "+f"(d[3])
        : "r"(a[0]), "r"(a[1]), "r"(a[2]), "r"(a[3]), "r"(b[0]), "r"(b[1]));
}
__device__ __forceinline__ void ldsm_x4(uint32_t* r, uint32_t addr) {
    asm volatile("ldmatrix.sync.aligned.m8n8.x4.shared.b16 {%0,%1,%2,%3}, [%4];"
                 : "=r"(r[0]), "=r"(r[1]), "=r"(r[2]), "=r"(r[3]) : "r"(addr));
}
__device__ __forceinline__ void cp_async16(uint32_t dst, const void* src, int szBytes) {
    asm volatile("cp.async.cg.shared.global [%0], [%1], 16, %2;"
                 :: "r"(dst), "l"(src), "r"(szBytes));
}
__device__ __forceinline__ void cp_async16f(uint32_t dst, const void* src) {
    asm volatile("cp.async.cg.shared.global [%0], [%1], 16;"
                 :: "r"(dst), "l"(src));
}
__device__ __forceinline__ void cp_commit() { asm volatile("cp.async.commit_group;" ::: "memory"); }
__device__ __forceinline__ void cp_wait1()  { asm volatile("cp.async.wait_group 1;" ::: "memory"); }
__device__ __forceinline__ void cp_wait0()  { asm volatile("cp.async.wait_group 0;" ::: "memory"); }

// ---------------- fp16-storage warp-mma GEMM (fp32 accumulate) ----------------
// C[M,N] = A[M,K] @ Wt[N,K]^T + bias
// mode 0: bias, fp32 out           mode 1: bias+GELU, fp16 out
// mode 2: bias+res, fp32 out       mode 3: bias, fp16 out
// mode 4: bias, fp16 out with unshift row-remap into [B*T, DIN] at col oColOff
// aPack: A rows gathered from [B*T_, DIN_] via roll(+aShift)+pad, col offset aColOff
#define GBM 128
#define GBN 256
#define GBK 64
#define ASTH 72
#define STAGE_H ((GBM + GBN) * ASTH)
#define GEMM_SMEM (3 * STAGE_H * 2)             // 165888 bytes

__device__ __forceinline__ void stage_loads(
    const __half* __restrict__ A, const __half* __restrict__ Wt,
    int M, int K, int rowBase, int colBase, int k0,
    uint32_t asBase, uint32_t bsBase, int tid,
    int aPack, int aShift, int aColOff)
{
    #pragma unroll
    for (int i = 0; i < 4; i++) {
        int idx = tid + i * 256;
        int r = idx >> 3, c = (idx & 7) << 3;
        int gr = rowBase + r;
        const __half* src;
        int sz;
        if (aPack) {
            int b = gr / TP_;
            int t = gr - b * TP_;
            int ts = t + aShift; if (ts >= TP_) ts -= TP_;
            sz = (gr < M && ts < T_) ? 16 : 0;
            if (ts >= T_) ts = 0;
            if (b >= B_) b = B_ - 1;
            src = A + ((size_t)b * T_ + ts) * DIN_ + aColOff + k0 + c;
        } else {
            sz = (gr < M) ? 16 : 0;
            if (gr >= M) gr = M - 1;
            src = A + (size_t)gr * K + k0 + c;
        }
        cp_async16(asBase + (uint32_t)(r * ASTH + c) * 2u, src, sz);
    }
    #pragma unroll
    for (int i = 0; i < 8; i++) {
        int idx = tid + i * 256;
        int r = idx >> 3, c = (idx & 7) << 3;
        cp_async16f(bsBase + (uint32_t)(r * ASTH + c) * 2u,
                    Wt + (size_t)(colBase + r) * K + k0 + c);
    }
    cp_commit();
}

__global__ __launch_bounds__(256, 1)
void mma_gemm(const __half* __restrict__ A, const __half* __restrict__ Wt,
              const float* __restrict__ bias, const float* __restrict__ res,
              void* __restrict__ Cv, int M, int N, int K, int mode,
              int aPack, int aShift, int aColOff, int oShift, int oColOff)
{
    extern __shared__ __half smh[];
    const uint32_t smBase = smem_u32(smh);

    const int tid  = threadIdx.x;
    const int wid  = tid >> 5;
    const int lane = tid & 31;
    const int g    = lane >> 2;
    const int tg   = lane & 3;
    const int warpRow = wid >> 2;
    const int warpCol = wid & 3;
    const int rowBase = blockIdx.y * GBM;
    const int colBase = blockIdx.x * GBN;

    float acc[4][8][4];
    #pragma unroll
    for (int mt = 0; mt < 4; mt++)
        #pragma unroll
        for (int nt = 0; nt < 8; nt++)
            #pragma unroll
            for (int i = 0; i < 4; i++) acc[mt][nt][i] = 0.f;

    const int nk = K >> 6;
    stage_loads(A, Wt, M, K, rowBase, colBase, 0,
                smBase, smBase + GBM * ASTH * 2u, tid, aPack, aShift, aColOff);
    if (nk > 1) {
        const uint32_t b1 = smBase + (uint32_t)STAGE_H * 2u;
        stage_loads(A, Wt, M, K, rowBase, colBase, GBK,
                    b1, b1 + GBM * ASTH * 2u, tid, aPack, aShift, aColOff);
    }

    const uint32_t aLaneOff = (uint32_t)((warpRow * 64 + (lane & 15)) * ASTH + (lane >> 4) * 8) * 2u;
    const uint32_t bLaneOff = (uint32_t)((warpCol * 64 + (lane & 7) + ((lane >> 4) << 3)) * ASTH
                                         + ((lane >> 3) & 1) * 8) * 2u;

    for (int kc = 0; kc < nk; kc++) {
        const int s = kc % 3;
        if (kc + 1 < nk) cp_wait1(); else cp_wait0();
        __syncthreads();
        // issue loads for stage kc+2 AFTER the barrier: its target buffer
        // ((kc+2)%3 == (kc-1)%3) was last read in iteration kc-1, which every
        // warp finished before this barrier.
        if (kc + 2 < nk) {
            const uint32_t nb = smBase + (uint32_t)(((kc + 2) % 3) * STAGE_H) * 2u;
            stage_loads(A, Wt, M, K, rowBase, colBase, (kc + 2) * GBK,
                        nb, nb + GBM * ASTH * 2u, tid, aPack, aShift, aColOff);
        }

        const uint32_t aBase = smBase + (uint32_t)(s * STAGE_H) * 2u + aLaneOff;
        const uint32_t bBase = smBase + (uint32_t)(s * STAGE_H + GBM * ASTH) * 2u + bLaneOff;

        #pragma unroll
        for (int ks = 0; ks < 4; ks++) {
            const uint32_t ko = (uint32_t)ks * 32u;
            uint32_t afr[4][4], bfr[8][2];
            #pragma unroll
            for (int mt = 0; mt < 4; mt++)
                ldsm_x4(afr[mt], aBase + (uint32_t)(mt * 16 * ASTH) * 2u + ko);
            #pragma unroll
            for (int ntp = 0; ntp < 4; ntp++) {
                uint32_t q[4];
                ldsm_x4(q, bBase + (uint32_t)(ntp * 16 * ASTH) * 2u + ko);
                bfr[2 * ntp + 0][0] = q[0]; bfr[2 * ntp + 0][1] = q[1];
                bfr[2 * ntp + 1][0] = q[2]; bfr[2 * ntp + 1][1] = q[3];
            }
            #pragma unroll
            for (int mt = 0; mt < 4; mt++)
                #pragma unroll
                for (int nt = 0; nt < 8; nt++)
                    mma_f16(acc[mt][nt], afr[mt], bfr[nt]);
        }
    }

    // ---------------- epilogue ----------------
    float* Cf = (float*)Cv;
    __half* Ch = (__half*)Cv;
    #pragma unroll
    for (int mt = 0; mt < 4; mt++) {
        #pragma unroll
        for (int nt = 0; nt < 8; nt++) {
            const int r0 = rowBase + warpRow * 64 + mt * 16 + g;
            const int cc = colBase + warpCol * 64 + nt * 8 + 2 * tg;
            const float bx = bias[cc], by = bias[cc + 1];
            #pragma unroll
            for (int h = 0; h < 2; h++) {
                const int row = r0 + h * 8;
                if (row >= M) continue;
                float v0 = acc[mt][nt][2 * h + 0] + bx;
                float v1 = acc[mt][nt][2 * h + 1] + by;
                if (mode == 1) {
                    v0 = 0.5f * v0 * (1.0f + erff(v0 * 0.70710678118654752f));
                    v1 = 0.5f * v1 * (1.0f + erff(v1 * 0.70710678118654752f));
                    *(__half2*)(Ch + (size_t)row * N + cc) = __floats2half2_rn(v0, v1);
                } else if (mode == 3) {
                    *(__half2*)(Ch + (size_t)row * N + cc) = __floats2half2_rn(v0, v1);
                } else if (mode == 4) {
                    int b = row / TP_;
                    int r = row - b * TP_;
                    int t = r + oShift; if (t >= TP_) t -= TP_;
                    if (t < T_)
                        *(__half2*)(Ch + ((size_t)b * T_ + t) * DIN_ + oColOff + cc) =
                            __floats2half2_rn(v0, v1);
                } else {
                    if (mode == 2) {
                        const float2 rv = *(const float2*)(res + (size_t)row * N + cc);
                        v0 += rv.x; v1 += rv.y;
                    }
                    *(float2*)(Cf + (size_t)row * N + cc) = make_float2(v0, v1);
                }
            }
        }
    }
}

// ---------------- fused prep: 8 weight transposes + x f2h ----
struct PrepArgs {
    const float* src[8];
    uint32_t     dstOff[8];
    int          K[8], N[8], tiles[8];
    const float* x;
    int          n8;
};
#define F2H_BLOCKS 16384

__global__ __launch_bounds__(256)
void prep_kernel(PrepArgs pa)
{
    const int tid = threadIdx.x;
    int bid = blockIdx.x;
    if (bid < F2H_BLOCKS) {
        __half* xh = g_xh;
        int idx = bid * 256 + tid;
        if (idx < pa.n8) {
            const float4* p = (const float4*)(pa.x + (size_t)idx * 8);
            float4 a = p[0], b = p[1];
            uint4 u;
            u.x = h2pack(a.x, a.y); u.y = h2pack(a.z, a.w);
            u.z = h2pack(b.x, b.y); u.w = h2pack(b.z, b.w);
            *(uint4*)(xh + (size_t)idx * 8) = u;
        }
        return;
    }
    bid -= F2H_BLOCKS;
    int e = 0;
    #pragma unroll
    for (int i = 0; i < 8; i++) {
        if (bid >= pa.tiles[i] && e == i) { bid -= pa.tiles[i]; e = i + 1; }
    }
    const float* src = pa.src[e];
    __half* dst = g_wt + pa.dstOff[e];
    const int K = pa.K[e], N = pa.N[e];
    const int tilesX = N >> 5;
    const int nb = (bid % tilesX) << 5;
    const int kb = (bid / tilesX) << 5;

    __shared__ float t[32][33];
    const int x = tid & 31, y = tid >> 5;
    #pragma unroll
    for (int i = 0; i < 32; i += 8)
        t[y + i][x] = src[(size_t)(kb + y + i) * N + nb + x];
    __syncthreads();
    #pragma unroll
    for (int i = 0; i < 32; i += 8)
        dst[(size_t)(nb + y + i) * K + kb + x] = __float2half(t[x][y + i]);
}

// ---------------- RMSNorm: fp32 in, fp16 out ----------------
__global__ void rmsnorm_kernel(const float* __restrict__ in, const float* __restrict__ w,
                               __half* __restrict__ out, int C)
{
    const int row = blockIdx.x;
    const float4* p4 = (const float4*)(in + (size_t)row * C);
    const float4* w4 = (const float4*)w;
    const int C4 = C >> 2;
    float s = 0.f;
    for (int c = threadIdx.x; c < C4; c += blockDim.x) {
        float4 v = p4[c];
        s += v.x * v.x + v.y * v.y + v.z * v.z + v.w * v.w;
    }
    #pragma unroll
    for (int o = 16; o > 0; o >>= 1) s += __shfl_xor_sync(0xffffffffu, s, o);
    __shared__ float red[8];
    __shared__ float scale;
    int wid = threadIdx.x >> 5, lane = threadIdx.x & 31;
    if (lane == 0) red[wid] = s;
    __syncthreads();
    if (threadIdx.x == 0) {
        float t = 0.f;
        for (int i = 0; i < (int)(blockDim.x >> 5); i++) t += red[i];
        scale = rsqrtf(t / (float)C + 1e-6f);
    }
    __syncthreads();
    float sc = scale;
    for (int c = threadIdx.x; c < C4; c += blockDim.x) {
        float4 v = p4[c], ww = w4[c];
        uint2 u;
        u.x = h2pack(v.x * sc * ww.x, v.y * sc * ww.y);
        u.y = h2pack(v.z * sc * ww.z, v.w * sc * ww.w);
        *(uint2*)(out + (size_t)row * C + c * 4) = u;
    }
}

// ---------------- windowed attention, templated (warp per b,window,head) ----------
template <int W, int NW, int SHIFT>
__global__ __launch_bounds__(128)
void attn_kernel(const __half* __restrict__ qkv, __half* __restrict__ ao,
                 const float* __restrict__ rpb)
{
    constexpr int SLICE = 3 * W * 32 + W * W + 8;
    __shared__ float sm[4 * SLICE];
    const int warp = threadIdx.x >> 5, lane = threadIdx.x & 31;
    float* S = sm + warp * SLICE;
    const int gw = blockIdx.x * 4 + warp;
    const int h = gw & 7;
    const int n = (gw >> 3) % NW;
    const int b = gw / (8 * NW);

    float* q  = S;
    float* k  = S + W * 32;
    float* v  = S + 2 * W * 32;
    float* lg = S + 3 * W * 32;

    const size_t rbase = (size_t)b * TP_ + (size_t)n * W;
    #pragma unroll
    for (int i = 0; i < W; i++) {
        size_t ro = (rbase + i) * 768 + h * 32 + lane;
        q[i * 32 + lane] = __half2float(qkv[ro]);
        k[i * 32 + lane] = __half2float(qkv[ro + 256]);
        v[i * 32 + lane] = __half2float(qkv[ro + 512]);
    }
    __syncwarp();

    const float scale = 0.17677669529663687f;
    const bool lastwin = (n == NW - 1);
    for (int p = lane; p < W * W; p += 32) {
        int i = p / W, j = p % W;
        float s = 0.f;
        #pragma unroll
        for (int d = 0; d < 32; d++) s = fmaf(q[i * 32 + d], k[j * 32 + d], s);
        s *= scale;
        s += rpb[(i - j + W - 1) * 8 + h];
        if (lastwin) {
            int mi = (i >= W - SHIFT) ? 2 : 1;
            int mj = (j >= W - SHIFT) ? 2 : 1;
            if (mi != mj) s -= 100.f;
        }
        lg[p] = s;
    }
    __syncwarp();

    if (lane < W) {
        float mx = -3.0e38f;
        #pragma unroll
        for (int j = 0; j < W; j++) mx = fmaxf(mx, lg[lane * W + j]);
        float sum = 0.f;
        #pragma unroll
        for (int j = 0; j < W; j++) {
            float e = __expf(lg[lane * W + j] - mx);
            lg[lane * W + j] = e; sum += e;
        }
        float inv = 1.f / sum;
        #pragma unroll
        for (int j = 0; j < W; j++) lg[lane * W + j] *= inv;
    }
    __syncwarp();

    #pragma unroll
    for (int i = 0; i < W; i++) {
        float a = 0.f;
        #pragma unroll
        for (int j = 0; j < W; j++) a = fmaf(lg[i * W + j], v[j * 32 + lane], a);
        ao[(rbase + i) * 256 + h * 32 + lane] = __float2half(a);
    }
}

// ---------------- launch ----------------
extern "C" void kernel_launch(void* const* d_in, const int* in_sizes, int n_in,
                              void* d_out, int out_size)
{
    (void)in_sizes; (void)n_in; (void)out_size;
    const float* x       = (const float*)d_in[0];
    const float* down_w  = (const float*)d_in[1];
    const float* down_b  = (const float*)d_in[2];
    const float* up_w    = (const float*)d_in[3];
    const float* up_b    = (const float*)d_in[4];
    const float* n1w     = (const float*)d_in[5];
    const float* n2w     = (const float*)d_in[6];
    const float* qkv1_w  = (const float*)d_in[7];
    const float* qkv1_b  = (const float*)d_in[8];
    const float* proj1_w = (const float*)d_in[9];
    const float* proj1_b = (const float*)d_in[10];
    const float* rpb1    = (const float*)d_in[11];
    const float* qkv2_w  = (const float*)d_in[12];
    const float* qkv2_b  = (const float*)d_in[13];
    const float* proj2_w = (const float*)d_in[14];
    const float* proj2_b = (const float*)d_in[15];
    const float* rpb2    = (const float*)d_in[16];
    const float* ffn_w1  = (const float*)d_in[17];
    const float* ffn_b1  = (const float*)d_in[18];
    const float* ffn_w2  = (const float*)d_in[19];
    const float* ffn_b2  = (const float*)d_in[20];
    float* out = (float*)d_out;

    __half *xh, *xih, *qk1, *qk2, *ao1, *ao2, *xcat, *hbuf, *ffn, *wt;
    float *xi, *xmid;
    cudaGetSymbolAddress((void**)&xh,   g_xh);
    cudaGetSymbolAddress((void**)&xi,   g_xi);
    cudaGetSymbolAddress((void**)&xih,  g_xih);
    cudaGetSymbolAddress((void**)&qk1,  g_qkv1);
    cudaGetSymbolAddress((void**)&qk2,  g_qkv2);
    cudaGetSymbolAddress((void**)&ao1,  g_ao1);
    cudaGetSymbolAddress((void**)&ao2,  g_ao2);
    cudaGetSymbolAddress((void**)&xcat, g_xcat);
    cudaGetSymbolAddress((void**)&xmid, g_xmid);
    cudaGetSymbolAddress((void**)&hbuf, g_h);
    cudaGetSymbolAddress((void**)&ffn,  g_ffn);
    cudaGetSymbolAddress((void**)&wt,   g_wt);

    cudaFuncSetAttribute(mma_gemm, cudaFuncAttributeMaxDynamicSharedMemorySize, GEMM_SMEM);

    // lazily-created side streams + fork/join events (host-side resources only;
    // work and output are identical and deterministic on every call)
    static cudaStream_t s1 = nullptr, s2 = nullptr;
    static cudaEvent_t evFork = nullptr, evJ1 = nullptr, evJ2 = nullptr;
    if (s1 == nullptr) {
        cudaStreamCreateWithFlags(&s1, cudaStreamNonBlocking);
        cudaStreamCreateWithFlags(&s2, cudaStreamNonBlocking);
        cudaEventCreateWithFlags(&evFork, cudaEventDisableTiming);
        cudaEventCreateWithFlags(&evJ1,   cudaEventDisableTiming);
        cudaEventCreateWithFlags(&evJ2,   cudaEventDisableTiming);
    }

    const int MT = B_ * T_;    // 32768
    const int MP = B_ * TP_;   // 32800
    const int MT_TILES = MT / GBM;              // 256
    const int MP_TILES = (MP + GBM - 1) / GBM;  // 257

    // 0. fused prep: all transposes + f2h (one launch)
    PrepArgs pa;
    const float* srcs[8]  = { down_w, up_w, qkv1_w, qkv2_w, proj1_w, proj2_w, ffn_w1, ffn_w2 };
    const uint32_t offs[8] = { O_DOWN, O_UP, O_QKV1, O_QKV2, O_PROJ1, O_PROJ2, O_FFN1, O_FFN2 };
    const int Ks[8] = { DIM_, DIN_, DBR_, DBR_, DBR_, DBR_, DIM_, 2*DIM_ };
    const int Ns[8] = { DIN_, DIM_, 768,  768,  DBR_, DBR_, 2*DIM_, DIM_ };
    int totalTiles = 0;
    for (int i = 0; i < 8; i++) {
        pa.src[i] = srcs[i]; pa.dstOff[i] = offs[i];
        pa.K[i] = Ks[i]; pa.N[i] = Ns[i];
        pa.tiles[i] = (Ns[i] / 32) * (Ks[i] / 32);
        totalTiles += pa.tiles[i];
    }
    pa.x = x; pa.n8 = MT * DIM_ / 8;
    prep_kernel<<<F2H_BLOCKS + totalTiles, 256>>>(pa);

    // 1. down + rmsnorm1 (fp16 out)
    mma_gemm<<<dim3(DIN_/GBN, MT_TILES), 256, GEMM_SMEM>>>(
        xh, wt + O_DOWN, down_b, nullptr, xi, MT, DIN_, DIM_, 0, 0, 0, 0, 0, 0);
    rmsnorm_kernel<<<MT, 128>>>(xi, n1w, xih, DIN_);

    // ---- fork the two independent branch chains onto side streams ----
    cudaEventRecord(evFork, 0);
    cudaStreamWaitEvent(s1, evFork, 0);
    cudaStreamWaitEvent(s2, evFork, 0);

    // branch 1 (stream s1): qkv1 -> attn1 -> proj1(+unshift)
    mma_gemm<<<dim3(768/GBN, MP_TILES), 256, GEMM_SMEM, s1>>>(
        xih, wt + O_QKV1, qkv1_b, nullptr, qk1, MP, 768, DBR_, 3, 1, 5, 0, 0, 0);
    attn_kernel<10, NW1_, 5><<<B_ * NW1_ * HBR_ / 4, 128, 0, s1>>>(qk1, ao1, rpb1);
    mma_gemm<<<dim3(DBR_/GBN, MP_TILES), 256, GEMM_SMEM, s1>>>(
        ao1, wt + O_PROJ1, proj1_b, nullptr, xcat, MP, DBR_, DBR_, 4, 0, 0, 0, 5, 0);

    // branch 2 (stream s2): qkv2 -> attn2 -> proj2(+unshift)
    mma_gemm<<<dim3(768/GBN, MP_TILES), 256, GEMM_SMEM, s2>>>(
        xih, wt + O_QKV2, qkv2_b, nullptr, qk2, MP, 768, DBR_, 3, 1, 10, DBR_, 0, 0);
    attn_kernel<20, NW2_, 10><<<B_ * NW2_ * HBR_ / 4, 128, 0, s2>>>(qk2, ao2, rpb2);
    mma_gemm<<<dim3(DBR_/GBN, MP_TILES), 256, GEMM_SMEM, s2>>>(
        ao2, wt + O_PROJ2, proj2_b, nullptr, xcat, MP, DBR_, DBR_, 4, 0, 0, 0, 10, DBR_);

    // ---- join ----
    cudaEventRecord(evJ1, s1);
    cudaEventRecord(evJ2, s2);
    cudaStreamWaitEvent(0, evJ1, 0);
    cudaStreamWaitEvent(0, evJ2, 0);

    // 5. up + residual (fp32 out)
    mma_gemm<<<dim3(DIM_/GBN, MT_TILES), 256, GEMM_SMEM>>>(
        xcat, wt + O_UP, up_b, x, xmid, MT, DIM_, DIN_, 2, 0, 0, 0, 0, 0);

    // 6. rmsnorm2 (fp16 out)
    rmsnorm_kernel<<<MT, 256>>>(xmid, n2w, hbuf, DIM_);

    // 7. FFN1 + GELU (fp16 out)
    mma_gemm<<<dim3(2*DIM_/GBN, MT_TILES), 256, GEMM_SMEM>>>(
        hbuf, wt + O_FFN1, ffn_b1, nullptr, ffn, MT, 2*DIM_, DIM_, 1, 0, 0, 0, 0, 0);

    // 8. FFN2 + residual -> out (fp32)
    mma_gemm<<<dim3(DIM_/GBN, MT_TILES), 256, GEMM_SMEM>>>(
        ffn, wt + O_FFN2, ffn_b2, xmid, out, MT, DIM_, 2*DIM_, 2, 0, 0, 0, 0, 0);
}

// round 17
// speedup vs baseline: 1.1545x; 1.0112x over previous
#include <cuda_runtime.h>
#include <cuda_fp16.h>
#include <math.h>
#include <stdint.h>

// ---------------- problem constants ----------------
#define B_    8
#define T_    4096
#define DIM_  1024
#define DIN_  512
#define DBR_  256
#define HBR_  8
#define TP_   4100
#define NW1_  410
#define NW2_  205

// ---------------- device scratch (static) ----------------
__device__ __half g_xh  [B_*T_*DIM_];
__device__ float  g_xi  [B_*T_*DIN_];
__device__ __half g_xih [B_*T_*DIN_];
__device__ __half g_qkv1[B_*TP_*3*DBR_];
__device__ __half g_qkv2[B_*TP_*3*DBR_];
__device__ __half g_ao1 [B_*TP_*DBR_];
__device__ __half g_ao2 [B_*TP_*DBR_];
__device__ __half g_xcat[B_*T_*DIN_];
__device__ float  g_xmid[B_*T_*DIM_];
__device__ __half g_h   [B_*T_*DIM_];
__device__ __half g_ffn [B_*T_*2*DIM_];
__device__ __half g_wt  [5767168];

#define O_DOWN  0u
#define O_UP    524288u
#define O_QKV1  1048576u
#define O_QKV2  1245184u
#define O_PROJ1 1441792u
#define O_PROJ2 1507328u
#define O_FFN1  1572864u
#define O_FFN2  3670016u

// ---------------- PTX helpers ----------
__device__ __forceinline__ uint32_t smem_u32(const void* p) {
    uint32_t a;
    asm("{ .reg .u64 t; cvta.to.shared.u64 t, %1; cvt.u32.u64 %0, t; }" : "=r"(a) : "l"(p));
    return a;
}
__device__ __forceinline__ uint32_t h2pack(float lo, float hi) {
    __half2 h = __floats2half2_rn(lo, hi);
    return *reinterpret_cast<uint32_t*>(&h);
}
__device__ __forceinline__ void mma_f16(float* d, const uint32_t* a, const uint32_t* b) {
    asm volatile(
        "mma.sync.aligned.m16n8k16.row.col.f32.f16.f16.f32 "
        "{%0,%1,%2,%3}, {%4,%5,%6,%7}, {%8,%9}, {%0,%1,%2,%3};"
        : "+f"(d[0]), "+f"(d[1]), "+f"(d[2]), "+f"(d[3])
        : "r"(a[0]), "r"(a[1]), "r"(a[2]), "r"(a[3]), "r"(b[0]), "r"(b[1]));
}
__device__ __forceinline__ void ldsm_x4(uint32_t* r, uint32_t addr) {
    asm volatile("ldmatrix.sync.aligned.m8n8.x4.shared.b16 {%0,%1,%2,%3}, [%4];"
                 : "=r"(r[0]), "=r"(r[1]), "=r"(r[2]), "=r"(r[3]) : "r"(addr));
}
__device__ __forceinline__ void cp_async16(uint32_t dst, const void* src, int szBytes) {
    asm volatile("cp.async.cg.shared.global [%0], [%1], 16, %2;"
                 :: "r"(dst), "l"(src), "r"(szBytes));
}
__device__ __forceinline__ void cp_async16f(uint32_t dst, const void* src) {
    asm volatile("cp.async.cg.shared.global [%0], [%1], 16;"
                 :: "r"(dst), "l"(src));
}
__device__ __forceinline__ void cp_commit() { asm volatile("cp.async.commit_group;" ::: "memory"); }
__device__ __forceinline__ void cp_wait0()  { asm volatile("cp.async.wait_group 0;" ::: "memory"); }

// ---------------- fp16-storage warp-mma GEMM (fp32 accumulate) ----------------
// C[M,N] = A[M,K] @ Wt[N,K]^T + bias
// mode 0: bias, fp32 out           mode 1: bias+GELU, fp16 out
// mode 2: bias+res, fp32 out       mode 3: bias, fp16 out
// mode 4: bias, fp16 out with unshift row-remap into [B*T, DIN] at col oColOff
// aPack: A rows gathered from [B*T_, DIN_] via roll(+aShift)+pad, col offset aColOff
// CTA tile 128x256, 8 warps (2x4), warp tile 64x64, K-chunk 128, 2-stage cp.async.
// Requires N % 256 == 0, K % 128 == 0. M guarded.
#define GBM 128
#define GBN 256
#define GBK 128
#define ASTH 136                                // 128 + 8 pad halves (272B stride, conflict-free)
#define STAGE_H ((GBM + GBN) * ASTH)            // 52224 halves = 104448 B
#define GEMM_SMEM (2 * STAGE_H * 2)             // 208896 bytes

__device__ __forceinline__ void stage_loads(
    const __half* __restrict__ A, const __half* __restrict__ Wt,
    int M, int K, int rowBase, int colBase, int k0,
    uint32_t asBase, uint32_t bsBase, int tid,
    int aPack, int aShift, int aColOff)
{
    // A: 128 rows x 16 chunks(16B = 8 halves) = 2048 slots
    #pragma unroll
    for (int i = 0; i < 8; i++) {
        int idx = tid + i * 256;
        int r = idx >> 4, c = (idx & 15) << 3;
        int gr = rowBase + r;
        const __half* src;
        int sz;
        if (aPack) {
            int b = gr / TP_;
            int t = gr - b * TP_;
            int ts = t + aShift; if (ts >= TP_) ts -= TP_;
            sz = (gr < M && ts < T_) ? 16 : 0;
            if (ts >= T_) ts = 0;
            if (b >= B_) b = B_ - 1;
            src = A + ((size_t)b * T_ + ts) * DIN_ + aColOff + k0 + c;
        } else {
            sz = (gr < M) ? 16 : 0;
            if (gr >= M) gr = M - 1;
            src = A + (size_t)gr * K + k0 + c;
        }
        cp_async16(asBase + (uint32_t)(r * ASTH + c) * 2u, src, sz);
    }
    // B: 256 rows x 16 chunks = 4096 slots
    #pragma unroll
    for (int i = 0; i < 16; i++) {
        int idx = tid + i * 256;
        int r = idx >> 4, c = (idx & 15) << 3;
        cp_async16f(bsBase + (uint32_t)(r * ASTH + c) * 2u,
                    Wt + (size_t)(colBase + r) * K + k0 + c);
    }
    cp_commit();
}

__global__ __launch_bounds__(256, 1)
void mma_gemm(const __half* __restrict__ A, const __half* __restrict__ Wt,
              const float* __restrict__ bias, const float* __restrict__ res,
              void* __restrict__ Cv, int M, int N, int K, int mode,
              int aPack, int aShift, int aColOff, int oShift, int oColOff)
{
    extern __shared__ __half smh[];
    const uint32_t smBase = smem_u32(smh);

    const int tid  = threadIdx.x;
    const int wid  = tid >> 5;
    const int lane = tid & 31;
    const int g    = lane >> 2;
    const int tg   = lane & 3;
    const int warpRow = wid >> 2;
    const int warpCol = wid & 3;
    const int rowBase = blockIdx.y * GBM;
    const int colBase = blockIdx.x * GBN;

    float acc[4][8][4];
    #pragma unroll
    for (int mt = 0; mt < 4; mt++)
        #pragma unroll
        for (int nt = 0; nt < 8; nt++)
            #pragma unroll
            for (int i = 0; i < 4; i++) acc[mt][nt][i] = 0.f;

    const int nk = K >> 7;              // K / 128
    stage_loads(A, Wt, M, K, rowBase, colBase, 0,
                smBase, smBase + GBM * ASTH * 2u, tid, aPack, aShift, aColOff);

    const uint32_t aLaneOff = (uint32_t)((warpRow * 64 + (lane & 15)) * ASTH + (lane >> 4) * 8) * 2u;
    const uint32_t bLaneOff = (uint32_t)((warpCol * 64 + (lane & 7) + ((lane >> 4) << 3)) * ASTH
                                         + ((lane >> 3) & 1) * 8) * 2u;

    for (int kc = 0; kc < nk; kc++) {
        const int s = kc & 1;
        cp_wait0();                     // only stage kc is outstanding here
        __syncthreads();
        // issue stage kc+1 AFTER the barrier: its buffer ((kc+1)&1) was
        // consumed in iteration kc-1, which every warp finished before this
        // barrier (prologue case kc=0: buffer 1 is untouched).
        if (kc + 1 < nk) {
            const uint32_t nb = smBase + (uint32_t)(((kc + 1) & 1) * STAGE_H) * 2u;
            stage_loads(A, Wt, M, K, rowBase, colBase, (kc + 1) * GBK,
                        nb, nb + GBM * ASTH * 2u, tid, aPack, aShift, aColOff);
        }

        const uint32_t aBase = smBase + (uint32_t)(s * STAGE_H) * 2u + aLaneOff;
        const uint32_t bBase = smBase + (uint32_t)(s * STAGE_H + GBM * ASTH) * 2u + bLaneOff;

        #pragma unroll
        for (int ks = 0; ks < 8; ks++) {
            const uint32_t ko = (uint32_t)ks * 32u;     // 16 halves = 32 bytes
            uint32_t afr[4][4], bfr[8][2];
            #pragma unroll
            for (int mt = 0; mt < 4; mt++)
                ldsm_x4(afr[mt], aBase + (uint32_t)(mt * 16 * ASTH) * 2u + ko);
            #pragma unroll
            for (int ntp = 0; ntp < 4; ntp++) {
                uint32_t q[4];
                ldsm_x4(q, bBase + (uint32_t)(ntp * 16 * ASTH) * 2u + ko);
                bfr[2 * ntp + 0][0] = q[0]; bfr[2 * ntp + 0][1] = q[1];
                bfr[2 * ntp + 1][0] = q[2]; bfr[2 * ntp + 1][1] = q[3];
            }
            #pragma unroll
            for (int mt = 0; mt < 4; mt++)
                #pragma unroll
                for (int nt = 0; nt < 8; nt++)
                    mma_f16(acc[mt][nt], afr[mt], bfr[nt]);
        }
    }

    // ---------------- epilogue ----------------
    float* Cf = (float*)Cv;
    __half* Ch = (__half*)Cv;
    #pragma unroll
    for (int mt = 0; mt < 4; mt++) {
        #pragma unroll
        for (int nt = 0; nt < 8; nt++) {
            const int r0 = rowBase + warpRow * 64 + mt * 16 + g;
            const int cc = colBase + warpCol * 64 + nt * 8 + 2 * tg;
            const float bx = bias[cc], by = bias[cc + 1];
            #pragma unroll
            for (int h = 0; h < 2; h++) {
                const int row = r0 + h * 8;
                if (row >= M) continue;
                float v0 = acc[mt][nt][2 * h + 0] + bx;
                float v1 = acc[mt][nt][2 * h + 1] + by;
                if (mode == 1) {
                    v0 = 0.5f * v0 * (1.0f + erff(v0 * 0.70710678118654752f));
                    v1 = 0.5f * v1 * (1.0f + erff(v1 * 0.70710678118654752f));
                    *(__half2*)(Ch + (size_t)row * N + cc) = __floats2half2_rn(v0, v1);
                } else if (mode == 3) {
                    *(__half2*)(Ch + (size_t)row * N + cc) = __floats2half2_rn(v0, v1);
                } else if (mode == 4) {
                    int b = row / TP_;
                    int r = row - b * TP_;
                    int t = r + oShift; if (t >= TP_) t -= TP_;
                    if (t < T_)
                        *(__half2*)(Ch + ((size_t)b * T_ + t) * DIN_ + oColOff + cc) =
                            __floats2half2_rn(v0, v1);
                } else {
                    if (mode == 2) {
                        const float2 rv = *(const float2*)(res + (size_t)row * N + cc);
                        v0 += rv.x; v1 += rv.y;
                    }
                    *(float2*)(Cf + (size_t)row * N + cc) = make_float2(v0, v1);
                }
            }
        }
    }
}

// ---------------- prep: weight transposes (fp32->fp16 K-major) + optional f2h ----
struct PrepArgs {
    const float* src[8];
    uint32_t     dstOff[8];
    int          K[8], N[8], tiles[8];
    int          nw;          // number of weight entries
    const float* x;           // nullptr -> no f2h section
    int          n8;
    int          f2hBlocks;
};
#define F2H_BLOCKS 16384

__global__ __launch_bounds__(256)
void prep_kernel(PrepArgs pa)
{
    const int tid = threadIdx.x;
    int bid = blockIdx.x;
    if (bid < pa.f2hBlocks) {
        __half* xh = g_xh;
        int idx = bid * 256 + tid;
        if (idx < pa.n8) {
            const float4* p = (const float4*)(pa.x + (size_t)idx * 8);
            float4 a = p[0], b = p[1];
            uint4 u;
            u.x = h2pack(a.x, a.y); u.y = h2pack(a.z, a.w);
            u.z = h2pack(b.x, b.y); u.w = h2pack(b.z, b.w);
            *(uint4*)(xh + (size_t)idx * 8) = u;
        }
        return;
    }
    bid -= pa.f2hBlocks;
    int e = 0;
    for (int i = 0; i < pa.nw; i++) {
        if (bid >= pa.tiles[i] && e == i) { bid -= pa.tiles[i]; e = i + 1; }
    }
    const float* src = pa.src[e];
    __half* dst = g_wt + pa.dstOff[e];
    const int K = pa.K[e], N = pa.N[e];
    const int tilesX = N >> 5;
    const int nb = (bid % tilesX) << 5;
    const int kb = (bid / tilesX) << 5;

    __shared__ float t[32][33];
    const int x = tid & 31, y = tid >> 5;
    #pragma unroll
    for (int i = 0; i < 32; i += 8)
        t[y + i][x] = src[(size_t)(kb + y + i) * N + nb + x];
    __syncthreads();
    #pragma unroll
    for (int i = 0; i < 32; i += 8)
        dst[(size_t)(nb + y + i) * K + kb + x] = __float2half(t[x][y + i]);
}

// ---------------- RMSNorm: fp32 in, fp16 out ----------------
__global__ void rmsnorm_kernel(const float* __restrict__ in, const float* __restrict__ w,
                               __half* __restrict__ out, int C)
{
    const int row = blockIdx.x;
    const float4* p4 = (const float4*)(in + (size_t)row * C);
    const float4* w4 = (const float4*)w;
    const int C4 = C >> 2;
    float s = 0.f;
    for (int c = threadIdx.x; c < C4; c += blockDim.x) {
        float4 v = p4[c];
        s += v.x * v.x + v.y * v.y + v.z * v.z + v.w * v.w;
    }
    #pragma unroll
    for (int o = 16; o > 0; o >>= 1) s += __shfl_xor_sync(0xffffffffu, s, o);
    __shared__ float red[8];
    __shared__ float scale;
    int wid = threadIdx.x >> 5, lane = threadIdx.x & 31;
    if (lane == 0) red[wid] = s;
    __syncthreads();
    if (threadIdx.x == 0) {
        float t = 0.f;
        for (int i = 0; i < (int)(blockDim.x >> 5); i++) t += red[i];
        scale = rsqrtf(t / (float)C + 1e-6f);
    }
    __syncthreads();
    float sc = scale;
    for (int c = threadIdx.x; c < C4; c += blockDim.x) {
        float4 v = p4[c], ww = w4[c];
        uint2 u;
        u.x = h2pack(v.x * sc * ww.x, v.y * sc * ww.y);
        u.y = h2pack(v.z * sc * ww.z, v.w * sc * ww.w);
        *(uint2*)(out + (size_t)row * C + c * 4) = u;
    }
}

// ---------------- windowed attention, templated (warp per b,window,head) ----------
template <int W, int NW, int SHIFT>
__global__ __launch_bounds__(128)
void attn_kernel(const __half* __restrict__ qkv, __half* __restrict__ ao,
                 const float* __restrict__ rpb)
{
    constexpr int SLICE = 3 * W * 32 + W * W + 8;
    __shared__ float sm[4 * SLICE];
    const int warp = threadIdx.x >> 5, lane = threadIdx.x & 31;
    float* S = sm + warp * SLICE;
    const int gw = blockIdx.x * 4 + warp;
    const int h = gw & 7;
    const int n = (gw >> 3) % NW;
    const int b = gw / (8 * NW);

    float* q  = S;
    float* k  = S + W * 32;
    float* v  = S + 2 * W * 32;
    float* lg = S + 3 * W * 32;

    const size_t rbase = (size_t)b * TP_ + (size_t)n * W;
    #pragma unroll
    for (int i = 0; i < W; i++) {
        size_t ro = (rbase + i) * 768 + h * 32 + lane;
        q[i * 32 + lane] = __half2float(qkv[ro]);
        k[i * 32 + lane] = __half2float(qkv[ro + 256]);
        v[i * 32 + lane] = __half2float(qkv[ro + 512]);
    }
    __syncwarp();

    const float scale = 0.17677669529663687f;
    const bool lastwin = (n == NW - 1);
    for (int p = lane; p < W * W; p += 32) {
        int i = p / W, j = p % W;
        float s = 0.f;
        #pragma unroll
        for (int d = 0; d < 32; d++) s = fmaf(q[i * 32 + d], k[j * 32 + d], s);
        s *= scale;
        s += rpb[(i - j + W - 1) * 8 + h];
        if (lastwin) {
            int mi = (i >= W - SHIFT) ? 2 : 1;
            int mj = (j >= W - SHIFT) ? 2 : 1;
            if (mi != mj) s -= 100.f;
        }
        lg[p] = s;
    }
    __syncwarp();

    if (lane < W) {
        float mx = -3.0e38f;
        #pragma unroll
        for (int j = 0; j < W; j++) mx = fmaxf(mx, lg[lane * W + j]);
        float sum = 0.f;
        #pragma unroll
        for (int j = 0; j < W; j++) {
            float e = __expf(lg[lane * W + j] - mx);
            lg[lane * W + j] = e; sum += e;
        }
        float inv = 1.f / sum;
        #pragma unroll
        for (int j = 0; j < W; j++) lg[lane * W + j] *= inv;
    }
    __syncwarp();

    #pragma unroll
    for (int i = 0; i < W; i++) {
        float a = 0.f;
        #pragma unroll
        for (int j = 0; j < W; j++) a = fmaf(lg[i * W + j], v[j * 32 + lane], a);
        ao[(rbase + i) * 256 + h * 32 + lane] = __float2half(a);
    }
}

// ---------------- launch ----------------
extern "C" void kernel_launch(void* const* d_in, const int* in_sizes, int n_in,
                              void* d_out, int out_size)
{
    (void)in_sizes; (void)n_in; (void)out_size;
    const float* x       = (const float*)d_in[0];
    const float* down_w  = (const float*)d_in[1];
    const float* down_b  = (const float*)d_in[2];
    const float* up_w    = (const float*)d_in[3];
    const float* up_b    = (const float*)d_in[4];
    const float* n1w     = (const float*)d_in[5];
    const float* n2w     = (const float*)d_in[6];
    const float* qkv1_w  = (const float*)d_in[7];
    const float* qkv1_b  = (const float*)d_in[8];
    const float* proj1_w = (const float*)d_in[9];
    const float* proj1_b = (const float*)d_in[10];
    const float* rpb1    = (const float*)d_in[11];
    const float* qkv2_w  = (const float*)d_in[12];
    const float* qkv2_b  = (const float*)d_in[13];
    const float* proj2_w = (const float*)d_in[14];
    const float* proj2_b = (const float*)d_in[15];
    const float* rpb2    = (const float*)d_in[16];
    const float* ffn_w1  = (const float*)d_in[17];
    const float* ffn_b1  = (const float*)d_in[18];
    const float* ffn_w2  = (const float*)d_in[19];
    const float* ffn_b2  = (const float*)d_in[20];
    float* out = (float*)d_out;

    __half *xh, *xih, *qk1, *qk2, *ao1, *ao2, *xcat, *hbuf, *ffn, *wt;
    float *xi, *xmid;
    cudaGetSymbolAddress((void**)&xh,   g_xh);
    cudaGetSymbolAddress((void**)&xi,   g_xi);
    cudaGetSymbolAddress((void**)&xih,  g_xih);
    cudaGetSymbolAddress((void**)&qk1,  g_qkv1);
    cudaGetSymbolAddress((void**)&qk2,  g_qkv2);
    cudaGetSymbolAddress((void**)&ao1,  g_ao1);
    cudaGetSymbolAddress((void**)&ao2,  g_ao2);
    cudaGetSymbolAddress((void**)&xcat, g_xcat);
    cudaGetSymbolAddress((void**)&xmid, g_xmid);
    cudaGetSymbolAddress((void**)&hbuf, g_h);
    cudaGetSymbolAddress((void**)&ffn,  g_ffn);
    cudaGetSymbolAddress((void**)&wt,   g_wt);

    cudaFuncSetAttribute(mma_gemm, cudaFuncAttributeMaxDynamicSharedMemorySize, GEMM_SMEM);

    // lazily-created side streams + events (host-side resources only; the
    // recorded work is identical and deterministic on every call)
    static cudaStream_t s1 = nullptr, s2 = nullptr;
    static cudaEvent_t evStart = nullptr, evFork = nullptr,
                       evJ1 = nullptr, evJ2 = nullptr, evPrep = nullptr;
    if (s1 == nullptr) {
        cudaStreamCreateWithFlags(&s1, cudaStreamNonBlocking);
        cudaStreamCreateWithFlags(&s2, cudaStreamNonBlocking);
        cudaEventCreateWithFlags(&evStart, cudaEventDisableTiming);
        cudaEventCreateWithFlags(&evFork,  cudaEventDisableTiming);
        cudaEventCreateWithFlags(&evJ1,    cudaEventDisableTiming);
        cudaEventCreateWithFlags(&evJ2,    cudaEventDisableTiming);
        cudaEventCreateWithFlags(&evPrep,  cudaEventDisableTiming);
    }

    const int MT = B_ * T_;    // 32768
    const int MP = B_ * TP_;   // 32800
    const int MT_TILES = MT / GBM;              // 256
    const int MP_TILES = (MP + GBM - 1) / GBM;  // 257

    // ---- pull side stream s1 into the capture BEFORE launching on it ----
    cudaEventRecord(evStart, 0);
    cudaStreamWaitEvent(s1, evStart, 0);

    // 0a. side prep on s1: 7 non-down weight transposes (overlaps f2h + down GEMM)
    {
        PrepArgs pb;
        const float* srcs[7]  = { up_w, qkv1_w, qkv2_w, proj1_w, proj2_w, ffn_w1, ffn_w2 };
        const uint32_t offs[7] = { O_UP, O_QKV1, O_QKV2, O_PROJ1, O_PROJ2, O_FFN1, O_FFN2 };
        const int Ks[7] = { DIN_, DBR_, DBR_, DBR_, DBR_, DIM_, 2*DIM_ };
        const int Ns[7] = { DIM_, 768,  768,  DBR_, DBR_, 2*DIM_, DIM_ };
        int tot = 0;
        for (int i = 0; i < 7; i++) {
            pb.src[i] = srcs[i]; pb.dstOff[i] = offs[i];
            pb.K[i] = Ks[i]; pb.N[i] = Ns[i];
            pb.tiles[i] = (Ns[i] / 32) * (Ks[i] / 32);
            tot += pb.tiles[i];
        }
        pb.nw = 7; pb.x = nullptr; pb.n8 = 0; pb.f2hBlocks = 0;
        prep_kernel<<<tot, 256, 0, s1>>>(pb);
        cudaEventRecord(evPrep, s1);
    }

    // 0b. main prep: f2h(x) + down transpose
    {
        PrepArgs pm;
        pm.src[0] = down_w; pm.dstOff[0] = O_DOWN;
        pm.K[0] = DIM_; pm.N[0] = DIN_;
        pm.tiles[0] = (DIN_ / 32) * (DIM_ / 32);
        pm.nw = 1; pm.x = x; pm.n8 = MT * DIM_ / 8; pm.f2hBlocks = F2H_BLOCKS;
        prep_kernel<<<F2H_BLOCKS + pm.tiles[0], 256>>>(pm);
    }

    // 1. down + rmsnorm1 (fp16 out)
    mma_gemm<<<dim3(DIN_/GBN, MT_TILES), 256, GEMM_SMEM>>>(
        xh, wt + O_DOWN, down_b, nullptr, xi, MT, DIN_, DIM_, 0, 0, 0, 0, 0, 0);
    rmsnorm_kernel<<<MT, 128>>>(xi, n1w, xih, DIN_);

    // ---- fork the two independent branch chains onto side streams ----
    cudaEventRecord(evFork, 0);
    cudaStreamWaitEvent(s1, evFork, 0);   // s1 also needs xih from main stream
    cudaStreamWaitEvent(s2, evFork, 0);
    cudaStreamWaitEvent(s2, evPrep, 0);   // qkv2/proj2 weights come from side prep on s1

    // branch 1 (stream s1): qkv1 -> attn1 -> proj1(+unshift)
    mma_gemm<<<dim3(768/GBN, MP_TILES), 256, GEMM_SMEM, s1>>>(
        xih, wt + O_QKV1, qkv1_b, nullptr, qk1, MP, 768, DBR_, 3, 1, 5, 0, 0, 0);
    attn_kernel<10, NW1_, 5><<<B_ * NW1_ * HBR_ / 4, 128, 0, s1>>>(qk1, ao1, rpb1);
    mma_gemm<<<dim3(DBR_/GBN, MP_TILES), 256, GEMM_SMEM, s1>>>(
        ao1, wt + O_PROJ1, proj1_b, nullptr, xcat, MP, DBR_, DBR_, 4, 0, 0, 0, 5, 0);

    // branch 2 (stream s2): qkv2 -> attn2 -> proj2(+unshift)
    mma_gemm<<<dim3(768/GBN, MP_TILES), 256, GEMM_SMEM, s2>>>(
        xih, wt + O_QKV2, qkv2_b, nullptr, qk2, MP, 768, DBR_, 3, 1, 10, DBR_, 0, 0);
    attn_kernel<20, NW2_, 10><<<B_ * NW2_ * HBR_ / 4, 128, 0, s2>>>(qk2, ao2, rpb2);
    mma_gemm<<<dim3(DBR_/GBN, MP_TILES), 256, GEMM_SMEM, s2>>>(
        ao2, wt + O_PROJ2, proj2_b, nullptr, xcat, MP, DBR_, DBR_, 4, 0, 0, 0, 10, DBR_);

    // ---- join ----
    cudaEventRecord(evJ1, s1);
    cudaEventRecord(evJ2, s2);
    cudaStreamWaitEvent(0, evJ1, 0);
    cudaStreamWaitEvent(0, evJ2, 0);

    // 5. up + residual (fp32 out)
    mma_gemm<<<dim3(DIM_/GBN, MT_TILES), 256, GEMM_SMEM>>>(
        xcat, wt + O_UP, up_b, x, xmid, MT, DIM_, DIN_, 2, 0, 0, 0, 0, 0);

    // 6. rmsnorm2 (fp16 out)
    rmsnorm_kernel<<<MT, 256>>>(xmid, n2w, hbuf, DIM_);

    // 7. FFN1 + GELU (fp16 out)
    mma_gemm<<<dim3(2*DIM_/GBN, MT_TILES), 256, GEMM_SMEM>>>(
        hbuf, wt + O_FFN1, ffn_b1, nullptr, ffn, MT, 2*DIM_, DIM_, 1, 0, 0, 0, 0, 0);

    // 8. FFN2 + residual -> out (fp32)
    mma_gemm<<<dim3(DIM_/GBN, MT_TILES), 256, GEMM_SMEM>>>(
        ffn, wt + O_FFN2, ffn_b2, xmid, out, MT, DIM_, 2*DIM_, 2, 0, 0, 0, 0, 0);
}